// round 1
// baseline (speedup 1.0000x reference)
#include <cuda_runtime.h>
#include <cstdint>

// Problem constants
#define N_NODES 8192
#define T_DIM   256
#define F_DIM   128
#define C_DIM   32
#define NT_TOT  (N_NODES * T_DIM)   // 2097152
#define MAXDEG  512
#define LN_EPS  1e-5f

// ---------------- device scratch (static globals; no allocation) ----------------
__device__ float g_W1[C_DIM * T_DIM];     // W_mlp @ W_rel   [32,256]
__device__ float g_W2[C_DIM * T_DIM];     // W_mlp @ W_root  [32,256]
__device__ float g_bS[C_DIM];
__device__ float g_w1sum[C_DIM];
__device__ float g_w2sum[C_DIM];
__device__ float g_stats[2];              // mu, rstd
__device__ float g_part[2048];            // block partials for mean/var
__device__ float g_Y[N_NODES * C_DIM];    // Xn @ W1^T  [8192,32]
__device__ float g_Z[N_NODES * C_DIM];    // Xn @ W2^T + bS
__device__ int   g_nz[(size_t)N_NODES * MAXDEG];
__device__ int   g_cnt[N_NODES];
__device__ float g_dinv[N_NODES];
__device__ float g_s[N_NODES * C_DIM];    // softmax(S)
__device__ float g_rownum[N_NODES];
__device__ float g_rowden[N_NODES];
__device__ float g_sspart[256 * C_DIM];   // partials for s^T s

// ---------------- K1: partial sums of X (mean/var) ----------------
__global__ void k1_red(const float* __restrict__ X) {
    int tid = threadIdx.x;
    int g = blockIdx.x * 256 + tid;
    float s = 0.f, q = 0.f;
    for (int k = g; k < NT_TOT; k += 1024 * 256) {
        float x = X[k];
        s += x; q += x * x;
    }
    __shared__ float ss[256], sq[256];
    ss[tid] = s; sq[tid] = q;
    __syncthreads();
    for (int o = 128; o > 0; o >>= 1) {
        if (tid < o) { ss[tid] += ss[tid + o]; sq[tid] += sq[tid + o]; }
        __syncthreads();
    }
    if (tid == 0) {
        g_part[blockIdx.x] = ss[0];
        g_part[1024 + blockIdx.x] = sq[0];
    }
}

// ---------------- K2: finalize mu, rstd ----------------
__global__ void k2_stats() {
    int tid = threadIdx.x;  // 1024 threads
    __shared__ float ss[1024], sq[1024];
    ss[tid] = g_part[tid];
    sq[tid] = g_part[1024 + tid];
    __syncthreads();
    for (int o = 512; o > 0; o >>= 1) {
        if (tid < o) { ss[tid] += ss[tid + o]; sq[tid] += sq[tid + o]; }
        __syncthreads();
    }
    if (tid == 0) {
        float mu = ss[0] / (float)NT_TOT;
        float var = sq[0] / (float)NT_TOT - mu * mu;
        g_stats[0] = mu;
        g_stats[1] = rsqrtf(var + LN_EPS);
    }
}

// ---------------- K3: fold linear layers: W1 = Wmlp@Wrel, W2 = Wmlp@Wroot ----------------
__global__ void k3_w(const float* __restrict__ Wrel,
                     const float* __restrict__ Wroot,
                     const float* __restrict__ Wmlp) {
    int o = blockIdx.x * 256 + threadIdx.x;     // < 16384
    int m = o >> 13;
    int r = o & 8191;
    int c = r >> 8;
    int t = r & 255;
    const float* Wx = m ? Wroot : Wrel;
    float acc = 0.f;
    #pragma unroll 8
    for (int f = 0; f < F_DIM; f++)
        acc += Wmlp[c * F_DIM + f] * Wx[f * T_DIM + t];
    if (m) g_W2[c * T_DIM + t] = acc;
    else   g_W1[c * T_DIM + t] = acc;
}

// ---------------- K3b: bS, row-sums of W1/W2 ----------------
__global__ void k3b(const float* __restrict__ brel,
                    const float* __restrict__ bmlp,
                    const float* __restrict__ Wmlp) {
    int t = threadIdx.x;   // 96 threads
    if (t < 32) {
        float a = bmlp[t];
        for (int f = 0; f < F_DIM; f++) a += Wmlp[t * F_DIM + f] * brel[f];
        g_bS[t] = a;
    } else if (t < 64) {
        int c = t - 32;
        float a = 0.f;
        for (int tt = 0; tt < T_DIM; tt++) a += g_W1[c * T_DIM + tt];
        g_w1sum[c] = a;
    } else if (t < 96) {
        int c = t - 64;
        float a = 0.f;
        for (int tt = 0; tt < T_DIM; tt++) a += g_W2[c * T_DIM + tt];
        g_w2sum[c] = a;
    }
}

// ---------------- K4: Y = Xn@W1^T, Z = Xn@W2^T + bS  (LN folded) ----------------
// 256 blocks x 256 threads; 32 rows per block (8 warps x 4 rows); dynamic smem 96KB
__global__ void k4_yz(const float* __restrict__ X) {
    extern __shared__ float sm[];
    float* W1s = sm;                 // [256*32] transposed: W1s[t*32+c]
    float* W2s = sm + 8192;
    float* Xs  = sm + 16384;         // 32 rows * 256
    int tid = threadIdx.x, lane = tid & 31, w = tid >> 5;

    for (int o = tid; o < 8192; o += 256) {
        int t = o >> 5, c = o & 31;
        W1s[o] = g_W1[c * T_DIM + t];
        W2s[o] = g_W2[c * T_DIM + t];
    }
    int rbase = blockIdx.x * 32;
    const float4* xsrc = (const float4*)(X + (size_t)rbase * T_DIM);
    float4* xd = (float4*)Xs;
    for (int o = tid; o < 2048; o += 256) xd[o] = xsrc[o];
    __syncthreads();

    float mu = g_stats[0], rstd = g_stats[1];
    float aY0 = 0, aY1 = 0, aY2 = 0, aY3 = 0;
    float aZ0 = 0, aZ1 = 0, aZ2 = 0, aZ3 = 0;
    const float* x0 = Xs + (w * 4 + 0) * 256;
    const float* x1 = Xs + (w * 4 + 1) * 256;
    const float* x2 = Xs + (w * 4 + 2) * 256;
    const float* x3 = Xs + (w * 4 + 3) * 256;
    #pragma unroll 4
    for (int t = 0; t < 256; t++) {
        float w1 = W1s[t * 32 + lane], w2 = W2s[t * 32 + lane];
        float xa = x0[t], xb = x1[t], xc = x2[t], xe = x3[t];
        aY0 += xa * w1; aZ0 += xa * w2;
        aY1 += xb * w1; aZ1 += xb * w2;
        aY2 += xc * w1; aZ2 += xc * w2;
        aY3 += xe * w1; aZ3 += xe * w2;
    }
    float c1 = mu * g_w1sum[lane];
    float c2 = mu * g_w2sum[lane];
    float bs = g_bS[lane];
    int r0 = rbase + w * 4;
    g_Y[(r0 + 0) * 32 + lane] = rstd * (aY0 - c1);
    g_Y[(r0 + 1) * 32 + lane] = rstd * (aY1 - c1);
    g_Y[(r0 + 2) * 32 + lane] = rstd * (aY2 - c1);
    g_Y[(r0 + 3) * 32 + lane] = rstd * (aY3 - c1);
    g_Z[(r0 + 0) * 32 + lane] = rstd * (aZ0 - c2) + bs;
    g_Z[(r0 + 1) * 32 + lane] = rstd * (aZ1 - c2) + bs;
    g_Z[(r0 + 2) * 32 + lane] = rstd * (aZ2 - c2) + bs;
    g_Z[(r0 + 3) * 32 + lane] = rstd * (aZ3 - c2) + bs;
}

// ---------------- K5: single pass over A ----------------
// Per row: CSR build (deterministic), degree->dinv, gather of Y rows -> S, softmax -> s.
__global__ void k5_main(const float* __restrict__ A, float* __restrict__ out) {
    int i = blockIdx.x;
    int tid = threadIdx.x, lane = tid & 31, wid = tid >> 5;
    __shared__ int s_idx[MAXDEG];
    __shared__ int s_warp[8];
    __shared__ int s_total;
    __shared__ float s_red[256];

    const float4* arow = (const float4*)(A + (size_t)i * N_NODES);
    float4 v[8];
    int cbase = tid * 32;
    #pragma unroll
    for (int u = 0; u < 8; u++) v[u] = arow[tid * 8 + u];

    int cntL = 0;
    float vsum = 0.f;
    #pragma unroll
    for (int u = 0; u < 8; u++) {
        vsum += v[u].x + v[u].y + v[u].z + v[u].w;
        cntL += (v[u].x != 0.f) + (v[u].y != 0.f) + (v[u].z != 0.f) + (v[u].w != 0.f);
    }

    // deterministic block scan of per-thread counts
    int incl = cntL;
    for (int o = 1; o < 32; o <<= 1) {
        int n = __shfl_up_sync(0xffffffffu, incl, o);
        if (lane >= o) incl += n;
    }
    if (lane == 31) s_warp[wid] = incl;
    __syncthreads();
    if (tid < 8) {
        int wv = s_warp[tid];
        int inc = wv;
        for (int o = 1; o < 8; o <<= 1) {
            int n = __shfl_up_sync(0xffu, inc, o);
            if (tid >= o) inc += n;
        }
        if (tid == 7) s_total = inc;
        s_warp[tid] = inc - wv;   // exclusive warp offset
    }
    __syncthreads();

    int p = s_warp[wid] + (incl - cntL);
    #pragma unroll
    for (int u = 0; u < 8; u++) {
        if (v[u].x != 0.f && p < MAXDEG) s_idx[p++] = cbase + u * 4 + 0;
        if (v[u].y != 0.f && p < MAXDEG) s_idx[p++] = cbase + u * 4 + 1;
        if (v[u].z != 0.f && p < MAXDEG) s_idx[p++] = cbase + u * 4 + 2;
        if (v[u].w != 0.f && p < MAXDEG) s_idx[p++] = cbase + u * 4 + 3;
    }

    // degree (sum of values) via deterministic tree
    s_red[tid] = vsum;
    __syncthreads();
    for (int o = 128; o > 0; o >>= 1) {
        if (tid < o) s_red[tid] += s_red[tid + o];
        __syncthreads();
    }
    float deg = s_red[0];
    float dinv = rsqrtf(deg);
    int total = s_total;
    if (total > MAXDEG) total = MAXDEG;
    if (tid == 0) { g_cnt[i] = total; g_dinv[i] = dinv; }

    // write CSR row to global
    for (int k = tid; k < total; k += 256)
        g_nz[(size_t)i * MAXDEG + k] = s_idx[k];

    // gather: S[i,c] = sum_{j in nz(i)} Y[j,c]  (+ Z later)
    float acc = 0.f;
    #pragma unroll 2
    for (int k = wid; k < total; k += 8) {
        int j = s_idx[k];
        acc += g_Y[j * 32 + lane];
    }
    __syncthreads();               // protect s_red reuse (deg was read above)
    s_red[wid * 32 + lane] = acc;
    __syncthreads();

    if (tid < 32) {
        float Sv = g_Z[i * 32 + tid];
        #pragma unroll
        for (int w = 0; w < 8; w++) Sv += s_red[w * 32 + tid];
        out[(size_t)i * 32 + tid] = Sv;            // output S
        // warp softmax over 32 lanes
        float m = Sv;
        for (int o = 16; o > 0; o >>= 1) m = fmaxf(m, __shfl_xor_sync(0xffffffffu, m, o));
        float e = expf(Sv - m);
        float ssum = e;
        for (int o = 16; o > 0; o >>= 1) ssum += __shfl_xor_sync(0xffffffffu, ssum, o);
        g_s[i * 32 + tid] = e / ssum;
    }
}

// ---------------- K6: CSR second pass -> mincut numerator/denominator per row ----------------
__global__ void k6_pass2() {
    int tid = threadIdx.x, lane = tid & 31, w = tid >> 5;
    int i = blockIdx.x * 8 + w;
    __shared__ __align__(16) float s_sh[8][32];

    float si = g_s[i * 32 + lane];
    s_sh[w][lane] = si;
    __syncwarp();
    float nsq = si * si;
    for (int o = 16; o > 0; o >>= 1) nsq += __shfl_xor_sync(0xffffffffu, nsq, o);

    float di = g_dinv[i];
    int cnt = g_cnt[i];
    const size_t base = (size_t)i * MAXDEG;
    const float4* srow = (const float4*)&s_sh[w][0];
    float accn = 0.f, accd = 0.f;
    for (int k = lane; k < cnt; k += 32) {
        int j = g_nz[base + k];
        const float4* sj = (const float4*)(g_s + j * 32);
        float dot = 0.f;
        #pragma unroll
        for (int q = 0; q < 8; q++) {
            float4 a = srow[q];
            float4 b = sj[q];
            dot += a.x * b.x + a.y * b.y + a.z * b.z + a.w * b.w;
        }
        float dj = g_dinv[j];
        accn += dj * dot;
        accd += dj;
    }
    for (int o = 16; o > 0; o >>= 1) {
        accn += __shfl_xor_sync(0xffffffffu, accn, o);
        accd += __shfl_xor_sync(0xffffffffu, accd, o);
    }
    if (lane == 0) {
        g_rownum[i] = di * accn;           // dinv_i * sum_j dinv_j (s_i . s_j)
        g_rowden[i] = di * accd * nsq;     // d_norm_i * ||s_i||^2
    }
}

// ---------------- K7: partials of ss = s^T s ----------------
__global__ void k7_sspart() {
    int b = blockIdx.x;            // 256 blocks: c1 = b>>3, row-group rg = b&7
    int c1 = b >> 3, rg = b & 7;
    int tid = threadIdx.x;
    int c2 = tid & 31, rr = tid >> 5;
    float acc = 0.f;
    int iend = (rg + 1) * 1024;
    for (int i = rg * 1024 + rr; i < iend; i += 8)
        acc += g_s[i * 32 + c1] * g_s[i * 32 + c2];
    __shared__ float red[256];
    red[tid] = acc;
    __syncthreads();
    for (int o = 128; o >= 32; o >>= 1) {
        if (tid < o) red[tid] += red[tid + o];
        __syncthreads();
    }
    if (tid < 32) g_sspart[b * 32 + tid] = red[tid];
}

// ---------------- K8: final losses ----------------
__global__ void k8_final(float* __restrict__ out) {
    int tid = threadIdx.x;   // 1024 threads
    __shared__ float sd[1024];
    __shared__ float s_num, s_den, s_frob;

    float an = 0.f, ad = 0.f;
    for (int k = tid; k < N_NODES; k += 1024) {
        an += g_rownum[k];
        ad += g_rowden[k];
    }
    sd[tid] = an;
    __syncthreads();
    for (int o = 512; o > 0; o >>= 1) { if (tid < o) sd[tid] += sd[tid + o]; __syncthreads(); }
    if (tid == 0) s_num = sd[0];
    __syncthreads();
    sd[tid] = ad;
    __syncthreads();
    for (int o = 512; o > 0; o >>= 1) { if (tid < o) sd[tid] += sd[tid + o]; __syncthreads(); }
    if (tid == 0) s_den = sd[0];
    __syncthreads();

    // assemble ss element for this thread's (c1,c2)
    int c1 = tid >> 5, c2 = tid & 31;
    float ssv = 0.f;
    #pragma unroll
    for (int rg = 0; rg < 8; rg++)
        ssv += g_sspart[(c1 * 8 + rg) * 32 + c2];

    sd[tid] = ssv * ssv;
    __syncthreads();
    for (int o = 512; o > 0; o >>= 1) { if (tid < o) sd[tid] += sd[tid + o]; __syncthreads(); }
    if (tid == 0) s_frob = sqrtf(sd[0]);
    __syncthreads();

    float diff = ssv / s_frob - ((c1 == c2) ? rsqrtf((float)C_DIM) : 0.f);
    sd[tid] = diff * diff;
    __syncthreads();
    for (int o = 512; o > 0; o >>= 1) { if (tid < o) sd[tid] += sd[tid + o]; __syncthreads(); }

    if (tid == 0) {
        out[(size_t)N_NODES * C_DIM + 0] = -(s_num / s_den);   // loss_mc
        out[(size_t)N_NODES * C_DIM + 1] = sqrtf(sd[0]);       // loss_o
    }
}

// ---------------- launch ----------------
extern "C" void kernel_launch(void* const* d_in, const int* in_sizes, int n_in,
                              void* d_out, int out_size) {
    const float* X     = (const float*)d_in[0];
    const float* A     = (const float*)d_in[1];
    const float* Wrel  = (const float*)d_in[2];
    const float* brel  = (const float*)d_in[3];
    const float* Wroot = (const float*)d_in[4];
    const float* Wmlp  = (const float*)d_in[5];
    const float* bmlp  = (const float*)d_in[6];
    float* out = (float*)d_out;

    cudaFuncSetAttribute(k4_yz, cudaFuncAttributeMaxDynamicSharedMemorySize, 98304);

    k1_red<<<1024, 256>>>(X);
    k2_stats<<<1, 1024>>>();
    k3_w<<<64, 256>>>(Wrel, Wroot, Wmlp);
    k3b<<<1, 96>>>(brel, bmlp, Wmlp);
    k4_yz<<<256, 256, 98304>>>(X);
    k5_main<<<N_NODES, 256>>>(A, out);
    k6_pass2<<<N_NODES / 8, 256>>>();
    k7_sspart<<<256, 256>>>();
    k8_final<<<1, 1024>>>(out);
}

// round 3
// speedup vs baseline: 1.3805x; 1.3805x over previous
#include <cuda_runtime.h>
#include <cstdint>

// Problem constants
#define N_NODES 8192
#define T_DIM   256
#define F_DIM   128
#define C_DIM   32
#define NT_TOT  (N_NODES * T_DIM)   // 2097152
#define MAXDEG  512
#define LN_EPS  1e-5f

// ---------------- device scratch (static globals; no allocation) ----------------
__device__ float g_W1[C_DIM * T_DIM];     // W_mlp @ W_rel   [32,256]
__device__ float g_W2[C_DIM * T_DIM];     // W_mlp @ W_root  [32,256]
__device__ float g_bS[C_DIM];
__device__ float g_w1sum[C_DIM];
__device__ float g_w2sum[C_DIM];
__device__ float g_stats[2];              // mu, rstd
__device__ float g_part[2048];            // block partials for mean/var
__device__ float g_Y[N_NODES * C_DIM];    // Xn @ W1^T  [8192,32]
__device__ float g_Z[N_NODES * C_DIM];    // Xn @ W2^T + bS
__device__ int   g_nz[(size_t)N_NODES * MAXDEG];
__device__ int   g_cnt[N_NODES];
__device__ float g_dinv[N_NODES];
__device__ float g_s[N_NODES * C_DIM];    // softmax(S)
__device__ float g_rownum[N_NODES];
__device__ float g_rowden[N_NODES];
__device__ float g_sspart[256 * C_DIM];   // partials for s^T s

// ---------------- K1: partial sums of X (mean/var) ----------------
__global__ void k1_red(const float* __restrict__ X) {
    int tid = threadIdx.x;
    int g = blockIdx.x * 256 + tid;
    float s = 0.f, q = 0.f;
    for (int k = g; k < NT_TOT; k += 1024 * 256) {
        float x = X[k];
        s += x; q += x * x;
    }
    __shared__ float ss[256], sq[256];
    ss[tid] = s; sq[tid] = q;
    __syncthreads();
    for (int o = 128; o > 0; o >>= 1) {
        if (tid < o) { ss[tid] += ss[tid + o]; sq[tid] += sq[tid + o]; }
        __syncthreads();
    }
    if (tid == 0) {
        g_part[blockIdx.x] = ss[0];
        g_part[1024 + blockIdx.x] = sq[0];
    }
}

// ---------------- K2: finalize mu, rstd ----------------
__global__ void k2_stats() {
    int tid = threadIdx.x;  // 1024 threads
    __shared__ float ss[1024], sq[1024];
    ss[tid] = g_part[tid];
    sq[tid] = g_part[1024 + tid];
    __syncthreads();
    for (int o = 512; o > 0; o >>= 1) {
        if (tid < o) { ss[tid] += ss[tid + o]; sq[tid] += sq[tid + o]; }
        __syncthreads();
    }
    if (tid == 0) {
        float mu = ss[0] / (float)NT_TOT;
        float var = sq[0] / (float)NT_TOT - mu * mu;
        g_stats[0] = mu;
        g_stats[1] = rsqrtf(var + LN_EPS);
    }
}

// ---------------- K3: fold linear layers: W1 = Wmlp@Wrel, W2 = Wmlp@Wroot ----------------
__global__ void k3_w(const float* __restrict__ Wrel,
                     const float* __restrict__ Wroot,
                     const float* __restrict__ Wmlp) {
    int o = blockIdx.x * 256 + threadIdx.x;     // < 16384
    int m = o >> 13;
    int r = o & 8191;
    int c = r >> 8;
    int t = r & 255;
    const float* Wx = m ? Wroot : Wrel;
    float acc = 0.f;
    #pragma unroll 8
    for (int f = 0; f < F_DIM; f++)
        acc += Wmlp[c * F_DIM + f] * Wx[f * T_DIM + t];
    if (m) g_W2[c * T_DIM + t] = acc;
    else   g_W1[c * T_DIM + t] = acc;
}

// ---------------- K3b: bS, row-sums of W1/W2 (parallel: 3 blocks x 32 warps) ----------------
__global__ void k3b(const float* __restrict__ brel,
                    const float* __restrict__ bmlp,
                    const float* __restrict__ Wmlp) {
    int lane = threadIdx.x & 31;
    int c = threadIdx.x >> 5;        // warp id == output channel, 32 warps
    int which = blockIdx.x;          // 0: bS, 1: w1sum, 2: w2sum
    float a = 0.f;
    if (which == 0) {
        for (int f = lane; f < F_DIM; f += 32)
            a += Wmlp[c * F_DIM + f] * brel[f];
    } else {
        const float* W = (which == 1) ? g_W1 : g_W2;
        for (int t = lane; t < T_DIM; t += 32)
            a += W[c * T_DIM + t];
    }
    for (int o = 16; o > 0; o >>= 1) a += __shfl_xor_sync(0xffffffffu, a, o);
    if (lane == 0) {
        if (which == 0)      g_bS[c] = a + bmlp[c];
        else if (which == 1) g_w1sum[c] = a;
        else                 g_w2sum[c] = a;
    }
}

// ---------------- K4: Y = Xn@W1^T, Z = Xn@W2^T + bS  (LN folded) ----------------
// 256 blocks x 256 threads; 32 rows per block (8 warps x 4 rows); dynamic smem 96KB
__global__ void k4_yz(const float* __restrict__ X) {
    extern __shared__ float sm[];
    float* W1s = sm;                 // [256*32] transposed: W1s[t*32+c]
    float* W2s = sm + 8192;
    float* Xs  = sm + 16384;         // 32 rows * 256
    int tid = threadIdx.x, lane = tid & 31, w = tid >> 5;

    for (int o = tid; o < 8192; o += 256) {
        int t = o >> 5, c = o & 31;
        W1s[o] = g_W1[c * T_DIM + t];
        W2s[o] = g_W2[c * T_DIM + t];
    }
    int rbase = blockIdx.x * 32;
    const float4* xsrc = (const float4*)(X + (size_t)rbase * T_DIM);
    float4* xd = (float4*)Xs;
    for (int o = tid; o < 2048; o += 256) xd[o] = xsrc[o];
    __syncthreads();

    float mu = g_stats[0], rstd = g_stats[1];
    float aY0 = 0, aY1 = 0, aY2 = 0, aY3 = 0;
    float aZ0 = 0, aZ1 = 0, aZ2 = 0, aZ3 = 0;
    const float* x0 = Xs + (w * 4 + 0) * 256;
    const float* x1 = Xs + (w * 4 + 1) * 256;
    const float* x2 = Xs + (w * 4 + 2) * 256;
    const float* x3 = Xs + (w * 4 + 3) * 256;
    #pragma unroll 4
    for (int t = 0; t < 256; t++) {
        float w1 = W1s[t * 32 + lane], w2 = W2s[t * 32 + lane];
        float xa = x0[t], xb = x1[t], xc = x2[t], xe = x3[t];
        aY0 += xa * w1; aZ0 += xa * w2;
        aY1 += xb * w1; aZ1 += xb * w2;
        aY2 += xc * w1; aZ2 += xc * w2;
        aY3 += xe * w1; aZ3 += xe * w2;
    }
    float c1 = mu * g_w1sum[lane];
    float c2 = mu * g_w2sum[lane];
    float bs = g_bS[lane];
    int r0 = rbase + w * 4;
    g_Y[(r0 + 0) * 32 + lane] = rstd * (aY0 - c1);
    g_Y[(r0 + 1) * 32 + lane] = rstd * (aY1 - c1);
    g_Y[(r0 + 2) * 32 + lane] = rstd * (aY2 - c1);
    g_Y[(r0 + 3) * 32 + lane] = rstd * (aY3 - c1);
    g_Z[(r0 + 0) * 32 + lane] = rstd * (aZ0 - c2) + bs;
    g_Z[(r0 + 1) * 32 + lane] = rstd * (aZ1 - c2) + bs;
    g_Z[(r0 + 2) * 32 + lane] = rstd * (aZ2 - c2) + bs;
    g_Z[(r0 + 3) * 32 + lane] = rstd * (aZ3 - c2) + bs;
}

// ---------------- K5: single pass over A ----------------
// Per row: CSR build (deterministic, coalesced A read), deg = nnz count (A is 0/1),
// gather of Y rows -> S, softmax -> s.
__global__ void __launch_bounds__(256) k5_main(const float* __restrict__ A,
                                               float* __restrict__ out) {
    int i = blockIdx.x;
    int tid = threadIdx.x, lane = tid & 31, wid = tid >> 5;
    __shared__ int s_idx[MAXDEG];
    __shared__ int s_warp[8];
    __shared__ int s_total;
    __shared__ float s_red[256];

    // A row = 8192 floats = 2048 float4. 256 threads x 8 chunks, coalesced:
    // chunk u covers float4 indices [u*256, (u+1)*256).
    const float4* arow = (const float4*)(A + (size_t)i * N_NODES);
    float4 v[8];
    #pragma unroll
    for (int u = 0; u < 8; u++) v[u] = arow[u * 256 + tid];

    int cntL = 0;
    #pragma unroll
    for (int u = 0; u < 8; u++)
        cntL += (v[u].x != 0.f) + (v[u].y != 0.f) + (v[u].z != 0.f) + (v[u].w != 0.f);

    // deterministic block scan of per-thread counts
    int incl = cntL;
    for (int o = 1; o < 32; o <<= 1) {
        int n = __shfl_up_sync(0xffffffffu, incl, o);
        if (lane >= o) incl += n;
    }
    if (lane == 31) s_warp[wid] = incl;
    __syncthreads();
    if (tid < 8) {
        int wv = s_warp[tid];
        int inc = wv;
        for (int o = 1; o < 8; o <<= 1) {
            int n = __shfl_up_sync(0xffu, inc, o);
            if (tid >= o) inc += n;
        }
        if (tid == 7) s_total = inc;
        s_warp[tid] = inc - wv;   // exclusive warp offset
    }
    __syncthreads();

    int p = s_warp[wid] + (incl - cntL);
    #pragma unroll
    for (int u = 0; u < 8; u++) {
        int cbase = (u * 256 + tid) * 4;
        if (v[u].x != 0.f && p < MAXDEG) s_idx[p++] = cbase + 0;
        if (v[u].y != 0.f && p < MAXDEG) s_idx[p++] = cbase + 1;
        if (v[u].z != 0.f && p < MAXDEG) s_idx[p++] = cbase + 2;
        if (v[u].w != 0.f && p < MAXDEG) s_idx[p++] = cbase + 3;
    }
    __syncthreads();

    int total = s_total;
    if (total > MAXDEG) total = MAXDEG;
    float dinv = rsqrtf((float)total);      // A is 0/1: degree == nnz count
    if (tid == 0) { g_cnt[i] = total; g_dinv[i] = dinv; }

    // write CSR row to global
    for (int k = tid; k < total; k += 256)
        g_nz[(size_t)i * MAXDEG + k] = s_idx[k];

    // gather: S[i,c] = sum_{j in nz(i)} Y[j,c]  (+ Z later)
    float acc = 0.f;
    #pragma unroll 2
    for (int k = wid; k < total; k += 8) {
        int j = s_idx[k];
        acc += g_Y[j * 32 + lane];
    }
    s_red[wid * 32 + lane] = acc;
    __syncthreads();

    if (tid < 32) {
        float Sv = g_Z[i * 32 + tid];
        #pragma unroll
        for (int w = 0; w < 8; w++) Sv += s_red[w * 32 + tid];
        out[(size_t)i * 32 + tid] = Sv;            // output S
        // warp softmax over 32 lanes
        float m = Sv;
        for (int o = 16; o > 0; o >>= 1) m = fmaxf(m, __shfl_xor_sync(0xffffffffu, m, o));
        float e = expf(Sv - m);
        float ssum = e;
        for (int o = 16; o > 0; o >>= 1) ssum += __shfl_xor_sync(0xffffffffu, ssum, o);
        g_s[i * 32 + tid] = e / ssum;
    }
}

// ---------------- K6: CSR second pass -> mincut numerator/denominator per row ----------------
__global__ void k6_pass2() {
    int tid = threadIdx.x, lane = tid & 31, w = tid >> 5;
    int i = blockIdx.x * 8 + w;
    __shared__ __align__(16) float s_sh[8][32];

    float si = g_s[i * 32 + lane];
    s_sh[w][lane] = si;
    __syncwarp();
    float nsq = si * si;
    for (int o = 16; o > 0; o >>= 1) nsq += __shfl_xor_sync(0xffffffffu, nsq, o);

    float di = g_dinv[i];
    int cnt = g_cnt[i];
    const size_t base = (size_t)i * MAXDEG;
    const float4* srow = (const float4*)&s_sh[w][0];
    float accn = 0.f, accd = 0.f;
    for (int k = lane; k < cnt; k += 32) {
        int j = g_nz[base + k];
        const float4* sj = (const float4*)(g_s + j * 32);
        float dot = 0.f;
        #pragma unroll
        for (int q = 0; q < 8; q++) {
            float4 a = srow[q];
            float4 b = sj[q];
            dot += a.x * b.x + a.y * b.y + a.z * b.z + a.w * b.w;
        }
        float dj = g_dinv[j];
        accn += dj * dot;
        accd += dj;
    }
    for (int o = 16; o > 0; o >>= 1) {
        accn += __shfl_xor_sync(0xffffffffu, accn, o);
        accd += __shfl_xor_sync(0xffffffffu, accd, o);
    }
    if (lane == 0) {
        g_rownum[i] = di * accn;           // dinv_i * sum_j dinv_j (s_i . s_j)
        g_rowden[i] = di * accd * nsq;     // d_norm_i * ||s_i||^2
    }
}

// ---------------- K7: partials of ss = s^T s ----------------
__global__ void k7_sspart() {
    int b = blockIdx.x;            // 256 blocks: c1 = b>>3, row-group rg = b&7
    int c1 = b >> 3, rg = b & 7;
    int tid = threadIdx.x;
    int c2 = tid & 31, rr = tid >> 5;
    float acc = 0.f;
    int iend = (rg + 1) * 1024;
    for (int i = rg * 1024 + rr; i < iend; i += 8)
        acc += g_s[i * 32 + c1] * g_s[i * 32 + c2];
    __shared__ float red[256];
    red[tid] = acc;
    __syncthreads();
    for (int o = 128; o >= 32; o >>= 1) {
        if (tid < o) red[tid] += red[tid + o];
        __syncthreads();
    }
    if (tid < 32) g_sspart[b * 32 + tid] = red[tid];
}

// ---------------- K8: final losses ----------------
__global__ void k8_final(float* __restrict__ out) {
    int tid = threadIdx.x;   // 1024 threads
    __shared__ float sd[1024];
    __shared__ float s_num, s_den, s_frob;

    float an = 0.f, ad = 0.f;
    for (int k = tid; k < N_NODES; k += 1024) {
        an += g_rownum[k];
        ad += g_rowden[k];
    }
    sd[tid] = an;
    __syncthreads();
    for (int o = 512; o > 0; o >>= 1) { if (tid < o) sd[tid] += sd[tid + o]; __syncthreads(); }
    if (tid == 0) s_num = sd[0];
    __syncthreads();
    sd[tid] = ad;
    __syncthreads();
    for (int o = 512; o > 0; o >>= 1) { if (tid < o) sd[tid] += sd[tid + o]; __syncthreads(); }
    if (tid == 0) s_den = sd[0];
    __syncthreads();

    // assemble ss element for this thread's (c1,c2)
    int c1 = tid >> 5, c2 = tid & 31;
    float ssv = 0.f;
    #pragma unroll
    for (int rg = 0; rg < 8; rg++)
        ssv += g_sspart[(c1 * 8 + rg) * 32 + c2];

    sd[tid] = ssv * ssv;
    __syncthreads();
    for (int o = 512; o > 0; o >>= 1) { if (tid < o) sd[tid] += sd[tid + o]; __syncthreads(); }
    if (tid == 0) s_frob = sqrtf(sd[0]);
    __syncthreads();

    float diff = ssv / s_frob - ((c1 == c2) ? rsqrtf((float)C_DIM) : 0.f);
    sd[tid] = diff * diff;
    __syncthreads();
    for (int o = 512; o > 0; o >>= 1) { if (tid < o) sd[tid] += sd[tid + o]; __syncthreads(); }

    if (tid == 0) {
        out[(size_t)N_NODES * C_DIM + 0] = -(s_num / s_den);   // loss_mc
        out[(size_t)N_NODES * C_DIM + 1] = sqrtf(sd[0]);       // loss_o
    }
}

// ---------------- launch ----------------
extern "C" void kernel_launch(void* const* d_in, const int* in_sizes, int n_in,
                              void* d_out, int out_size) {
    const float* X     = (const float*)d_in[0];
    const float* A     = (const float*)d_in[1];
    const float* Wrel  = (const float*)d_in[2];
    const float* brel  = (const float*)d_in[3];
    const float* Wroot = (const float*)d_in[4];
    const float* Wmlp  = (const float*)d_in[5];
    const float* bmlp  = (const float*)d_in[6];
    float* out = (float*)d_out;

    cudaFuncSetAttribute(k4_yz, cudaFuncAttributeMaxDynamicSharedMemorySize, 98304);

    k1_red<<<1024, 256>>>(X);
    k2_stats<<<1, 1024>>>();
    k3_w<<<64, 256>>>(Wrel, Wroot, Wmlp);
    k3b<<<3, 1024>>>(brel, bmlp, Wmlp);
    k4_yz<<<256, 256, 98304>>>(X);
    k5_main<<<N_NODES, 256>>>(A, out);
    k6_pass2<<<N_NODES / 8, 256>>>();
    k7_sspart<<<256, 256>>>();
    k8_final<<<1, 1024>>>(out);
}

// round 4
// speedup vs baseline: 1.5016x; 1.0877x over previous
#include <cuda_runtime.h>
#include <cstdint>

// Problem constants
#define N_NODES 8192
#define T_DIM   256
#define F_DIM   128
#define C_DIM   32
#define NT_TOT  (N_NODES * T_DIM)   // 2097152
#define MAXDEG  512
#define LN_EPS  1e-5f

// ---------------- device scratch ----------------
__device__ float g_W1[C_DIM * T_DIM];     // W_mlp @ W_rel   [32,256]
__device__ float g_W2[C_DIM * T_DIM];     // W_mlp @ W_root  [32,256]
__device__ float g_bS[C_DIM];
__device__ float g_w1sum[C_DIM];
__device__ float g_w2sum[C_DIM];
__device__ float g_stats[2];              // mu, rstd
__device__ float g_part[2048];            // block partials for mean/var
__device__ int   g_arr1 = 0;              // arrival counter (stats)
__device__ int   g_arr2 = 0;              // arrival counter (k7k8)
__device__ float g_Y[N_NODES * C_DIM];    // Xn @ W1^T  [8192,32]
__device__ float g_Z[N_NODES * C_DIM];    // Xn @ W2^T + bS
__device__ int   g_nz[(size_t)N_NODES * MAXDEG];
__device__ int   g_cnt[N_NODES];
__device__ float g_dinv[N_NODES];
__device__ float g_s[N_NODES * C_DIM];    // softmax(S)
__device__ float g_rownum[N_NODES];
__device__ float g_rowden[N_NODES];
__device__ float g_sspart[256 * C_DIM];   // partials for s^T s

// ---------------- KA: X mean/var (fused two-phase, last-block finalize) ----------------
__global__ void kA_stats(const float* __restrict__ X) {
    int tid = threadIdx.x;
    int g = blockIdx.x * 256 + tid;
    float s = 0.f, q = 0.f;
    for (int k = g; k < NT_TOT; k += 1024 * 256) {
        float x = X[k];
        s += x; q += x * x;
    }
    __shared__ float ss[256], sq[256];
    ss[tid] = s; sq[tid] = q;
    __syncthreads();
    for (int o = 128; o > 0; o >>= 1) {
        if (tid < o) { ss[tid] += ss[tid + o]; sq[tid] += sq[tid + o]; }
        __syncthreads();
    }
    __shared__ bool isLast;
    if (tid == 0) {
        g_part[blockIdx.x] = ss[0];
        g_part[1024 + blockIdx.x] = sq[0];
        __threadfence();
        isLast = (atomicAdd(&g_arr1, 1) == 1023);
    }
    __syncthreads();
    if (!isLast) return;

    // final block: reduce 1024 partials (each thread sums 4, fixed order)
    float a = 0.f, b = 0.f;
    #pragma unroll
    for (int u = 0; u < 4; u++) {
        a += g_part[tid * 4 + u];
        b += g_part[1024 + tid * 4 + u];
    }
    ss[tid] = a; sq[tid] = b;
    __syncthreads();
    for (int o = 128; o > 0; o >>= 1) {
        if (tid < o) { ss[tid] += ss[tid + o]; sq[tid] += sq[tid + o]; }
        __syncthreads();
    }
    if (tid == 0) {
        float mu = ss[0] / (float)NT_TOT;
        float var = sq[0] / (float)NT_TOT - mu * mu;
        g_stats[0] = mu;
        g_stats[1] = rsqrtf(var + LN_EPS);
        g_arr1 = 0;                       // reset for next replay
    }
}

// ---------------- KB: weight folding (65 blocks; block 64 does bS/w1sum/w2sum) ----------------
__global__ void kB_weights(const float* __restrict__ Wrel,
                           const float* __restrict__ brel,
                           const float* __restrict__ Wroot,
                           const float* __restrict__ Wmlp,
                           const float* __restrict__ bmlp) {
    int tid = threadIdx.x;
    if (blockIdx.x < 64) {
        int o = blockIdx.x * 256 + tid;     // < 16384
        int m = o >> 13;
        int r = o & 8191;
        int c = r >> 8;
        int t = r & 255;
        const float* Wx = m ? Wroot : Wrel;
        float acc = 0.f;
        #pragma unroll 8
        for (int f = 0; f < F_DIM; f++)
            acc += Wmlp[c * F_DIM + f] * Wx[f * T_DIM + t];
        if (m) g_W2[c * T_DIM + t] = acc;
        else   g_W1[c * T_DIM + t] = acc;
        return;
    }
    // block 64: rowsums of Wrel/Wroot, then tiny dots with Wmlp
    __shared__ float rs[256];           // [0:128) rs_rel, [128:256) rs_root
    __shared__ float WmT[128 * 33];     // transposed Wmlp, padded stride 33
    int lane = tid & 31, w = tid >> 5;
    for (int o = tid; o < 4096; o += 256) {
        int c = o >> 7, f = o & 127;
        WmT[f * 33 + c] = Wmlp[o];
    }
    const float* src = (w < 4) ? Wrel : Wroot;
    int rbase = (w & 3) * 32;
    for (int r = rbase; r < rbase + 32; r++) {
        float a = 0.f;
        for (int t2 = lane; t2 < T_DIM; t2 += 32) a += src[r * T_DIM + t2];
        for (int o = 16; o > 0; o >>= 1) a += __shfl_xor_sync(0xffffffffu, a, o);
        if (lane == 0) rs[(w < 4 ? 0 : 128) + r] = a;
    }
    __syncthreads();
    if (tid < 96) {
        int c = tid & 31, which = tid >> 5;   // 0: w1sum, 1: w2sum, 2: bS
        float a = 0.f;
        if (which == 2) {
            for (int f = 0; f < F_DIM; f++) a += WmT[f * 33 + c] * brel[f];
            g_bS[c] = a + bmlp[c];
        } else {
            const float* rsp = rs + which * 128;
            for (int f = 0; f < F_DIM; f++) a += WmT[f * 33 + c] * rsp[f];
            if (which) g_w2sum[c] = a; else g_w1sum[c] = a;
        }
    }
}

// ---------------- K4: Y = Xn@W1^T, Z = Xn@W2^T + bS  (LN folded) ----------------
__global__ void k4_yz(const float* __restrict__ X) {
    extern __shared__ float sm[];
    float* W1s = sm;                 // [256*32] transposed: W1s[t*32+c]
    float* W2s = sm + 8192;
    float* Xs  = sm + 16384;         // 32 rows * 256
    int tid = threadIdx.x, lane = tid & 31, w = tid >> 5;

    for (int o = tid; o < 8192; o += 256) {
        int t = o >> 5, c = o & 31;
        W1s[o] = g_W1[c * T_DIM + t];
        W2s[o] = g_W2[c * T_DIM + t];
    }
    int rbase = blockIdx.x * 32;
    const float4* xsrc = (const float4*)(X + (size_t)rbase * T_DIM);
    float4* xd = (float4*)Xs;
    for (int o = tid; o < 2048; o += 256) xd[o] = xsrc[o];
    __syncthreads();

    float mu = g_stats[0], rstd = g_stats[1];
    float aY0 = 0, aY1 = 0, aY2 = 0, aY3 = 0;
    float aZ0 = 0, aZ1 = 0, aZ2 = 0, aZ3 = 0;
    const float* x0 = Xs + (w * 4 + 0) * 256;
    const float* x1 = Xs + (w * 4 + 1) * 256;
    const float* x2 = Xs + (w * 4 + 2) * 256;
    const float* x3 = Xs + (w * 4 + 3) * 256;
    #pragma unroll 4
    for (int t = 0; t < 256; t++) {
        float w1 = W1s[t * 32 + lane], w2 = W2s[t * 32 + lane];
        float xa = x0[t], xb = x1[t], xc = x2[t], xe = x3[t];
        aY0 += xa * w1; aZ0 += xa * w2;
        aY1 += xb * w1; aZ1 += xb * w2;
        aY2 += xc * w1; aZ2 += xc * w2;
        aY3 += xe * w1; aZ3 += xe * w2;
    }
    float c1 = mu * g_w1sum[lane];
    float c2 = mu * g_w2sum[lane];
    float bs = g_bS[lane];
    int r0 = rbase + w * 4;
    g_Y[(r0 + 0) * 32 + lane] = rstd * (aY0 - c1);
    g_Y[(r0 + 1) * 32 + lane] = rstd * (aY1 - c1);
    g_Y[(r0 + 2) * 32 + lane] = rstd * (aY2 - c1);
    g_Y[(r0 + 3) * 32 + lane] = rstd * (aY3 - c1);
    g_Z[(r0 + 0) * 32 + lane] = rstd * (aZ0 - c2) + bs;
    g_Z[(r0 + 1) * 32 + lane] = rstd * (aZ1 - c2) + bs;
    g_Z[(r0 + 2) * 32 + lane] = rstd * (aZ2 - c2) + bs;
    g_Z[(r0 + 3) * 32 + lane] = rstd * (aZ3 - c2) + bs;
}

// ---------------- K5: single pass over A (bitmask CSR build) ----------------
__global__ void __launch_bounds__(256) k5_main(const float* __restrict__ A,
                                               float* __restrict__ out) {
    int i = blockIdx.x;
    int tid = threadIdx.x, lane = tid & 31, wid = tid >> 5;
    __shared__ int s_idx[MAXDEG];
    __shared__ int s_warp[8];
    __shared__ int s_total;
    __shared__ float s_red[256];

    // A row = 2048 float4; chunk u covers [u*256, (u+1)*256), coalesced.
    const float4* arow = (const float4*)(A + (size_t)i * N_NODES);
    unsigned mask = 0;
    #pragma unroll
    for (int u = 0; u < 8; u++) {
        float4 v = arow[u * 256 + tid];
        unsigned b = (v.x != 0.f) | ((v.y != 0.f) << 1) |
                     ((v.z != 0.f) << 2) | ((v.w != 0.f) << 3);
        mask |= b << (u * 4);
    }
    int cntL = __popc(mask);

    // deterministic block scan of per-thread counts
    int incl = cntL;
    for (int o = 1; o < 32; o <<= 1) {
        int n = __shfl_up_sync(0xffffffffu, incl, o);
        if (lane >= o) incl += n;
    }
    if (lane == 31) s_warp[wid] = incl;
    __syncthreads();
    if (tid < 8) {
        int wv = s_warp[tid];
        int inc = wv;
        for (int o = 1; o < 8; o <<= 1) {
            int n = __shfl_up_sync(0xffu, inc, o);
            if (tid >= o) inc += n;
        }
        if (tid == 7) s_total = inc;
        s_warp[tid] = inc - wv;   // exclusive warp offset
    }
    __syncthreads();

    int p = s_warp[wid] + (incl - cntL);
    unsigned m = mask;
    while (m) {
        int b = __ffs(m) - 1;
        m &= m - 1;
        // bit (u*4+q) -> column (u*256+tid)*4 + q  == u*1024 + tid*4 + q
        int col = ((b >> 2) << 10) + (tid << 2) + (b & 3);
        if (p < MAXDEG) s_idx[p++] = col;
    }
    __syncthreads();

    int total = s_total;
    if (total > MAXDEG) total = MAXDEG;
    float dinv = rsqrtf((float)total);      // A is 0/1: degree == nnz
    if (tid == 0) { g_cnt[i] = total; g_dinv[i] = dinv; }

    // write CSR row
    for (int k = tid; k < total; k += 256)
        g_nz[(size_t)i * MAXDEG + k] = s_idx[k];

    // gather: S[i,c] = sum_{j in nz(i)} Y[j,c]
    float acc = 0.f;
    #pragma unroll 2
    for (int k = wid; k < total; k += 8) {
        int j = s_idx[k];
        acc += g_Y[j * 32 + lane];
    }
    s_red[wid * 32 + lane] = acc;
    __syncthreads();

    if (tid < 32) {
        float Sv = g_Z[i * 32 + tid];
        #pragma unroll
        for (int w = 0; w < 8; w++) Sv += s_red[w * 32 + tid];
        out[(size_t)i * 32 + tid] = Sv;            // output S
        float mx = Sv;
        for (int o = 16; o > 0; o >>= 1) mx = fmaxf(mx, __shfl_xor_sync(0xffffffffu, mx, o));
        float e = expf(Sv - mx);
        float ssum = e;
        for (int o = 16; o > 0; o >>= 1) ssum += __shfl_xor_sync(0xffffffffu, ssum, o);
        g_s[i * 32 + tid] = e / ssum;
    }
}

// ---------------- K6: mincut row terms (warp/row, coalesced s_j loads) ----------------
__global__ void k6_pass2() {
    int tid = threadIdx.x, lane = tid & 31, w = tid >> 5;
    int i = blockIdx.x * 8 + w;

    float si = g_s[i * 32 + lane];
    float nsq = si * si;
    for (int o = 16; o > 0; o >>= 1) nsq += __shfl_xor_sync(0xffffffffu, nsq, o);

    float di = g_dinv[i];
    int cnt = g_cnt[i];
    const size_t base = (size_t)i * MAXDEG;
    float accn = 0.f, accd = 0.f;

    for (int kk = 0; kk < cnt; kk += 32) {
        int valid = (kk + lane) < cnt;
        int idx = valid ? g_nz[base + kk + lane] : 0;
        float dv = valid ? g_dinv[idx] : 0.f;
        int mrem = cnt - kk; if (mrem > 32) mrem = 32;
        for (int e = 0; e < mrem; e++) {
            int j    = __shfl_sync(0xffffffffu, idx, e);
            float dj = __shfl_sync(0xffffffffu, dv, e);
            float sj = g_s[j * 32 + lane];            // coalesced 128B
            accn += dj * si * sj;
        }
        float t = dv;
        for (int o = 16; o > 0; o >>= 1) t += __shfl_xor_sync(0xffffffffu, t, o);
        accd += t;                                     // uniform across lanes
    }
    for (int o = 16; o > 0; o >>= 1) accn += __shfl_xor_sync(0xffffffffu, accn, o);
    if (lane == 0) {
        g_rownum[i] = di * accn;
        g_rowden[i] = di * accd * nsq;
    }
}

// ---------------- K7+K8 fused: s^T s partials, last block computes losses ----------------
__global__ void k7k8(float* __restrict__ out) {
    int b = blockIdx.x;            // 256 blocks: c1 = b>>3, row-group rg = b&7
    int c1 = b >> 3, rg = b & 7;
    int tid = threadIdx.x;
    int c2 = tid & 31, rr = tid >> 5;
    float acc = 0.f;
    int iend = (rg + 1) * 1024;
    for (int i = rg * 1024 + rr; i < iend; i += 8)
        acc += g_s[i * 32 + c1] * g_s[i * 32 + c2];
    __shared__ float red[256];
    red[tid] = acc;
    __syncthreads();
    for (int o = 128; o >= 32; o >>= 1) {
        if (tid < o) red[tid] += red[tid + o];
        __syncthreads();
    }
    if (tid < 32) g_sspart[b * 32 + tid] = red[tid];

    __shared__ bool isLast;
    if (tid == 0) {
        __threadfence();
        isLast = (atomicAdd(&g_arr2, 1) == 255);
    }
    __syncthreads();
    if (!isLast) return;

    // ---- final: losses (256 threads) ----
    __shared__ float sd[256];
    __shared__ float s_num, s_den, s_frob;

    float an = 0.f, ad = 0.f;
    for (int k = tid; k < N_NODES; k += 256) {
        an += g_rownum[k];
        ad += g_rowden[k];
    }
    sd[tid] = an;
    __syncthreads();
    for (int o = 128; o > 0; o >>= 1) { if (tid < o) sd[tid] += sd[tid + o]; __syncthreads(); }
    if (tid == 0) s_num = sd[0];
    __syncthreads();
    sd[tid] = ad;
    __syncthreads();
    for (int o = 128; o > 0; o >>= 1) { if (tid < o) sd[tid] += sd[tid + o]; __syncthreads(); }
    if (tid == 0) s_den = sd[0];
    __syncthreads();

    // each thread owns 4 entries of ss (1024 total)
    float ssv[4];
    float fr = 0.f;
    #pragma unroll
    for (int u = 0; u < 4; u++) {
        int e = tid * 4 + u;
        int e1 = e >> 5, e2 = e & 31;
        float v = 0.f;
        #pragma unroll
        for (int r = 0; r < 8; r++)
            v += g_sspart[(e1 * 8 + r) * 32 + e2];
        ssv[u] = v;
        fr += v * v;
    }
    sd[tid] = fr;
    __syncthreads();
    for (int o = 128; o > 0; o >>= 1) { if (tid < o) sd[tid] += sd[tid + o]; __syncthreads(); }
    if (tid == 0) s_frob = sqrtf(sd[0]);
    __syncthreads();

    float dsum = 0.f;
    #pragma unroll
    for (int u = 0; u < 4; u++) {
        int e = tid * 4 + u;
        int e1 = e >> 5, e2 = e & 31;
        float diff = ssv[u] / s_frob - ((e1 == e2) ? rsqrtf((float)C_DIM) : 0.f);
        dsum += diff * diff;
    }
    sd[tid] = dsum;
    __syncthreads();
    for (int o = 128; o > 0; o >>= 1) { if (tid < o) sd[tid] += sd[tid + o]; __syncthreads(); }

    if (tid == 0) {
        out[(size_t)N_NODES * C_DIM + 0] = -(s_num / s_den);   // loss_mc
        out[(size_t)N_NODES * C_DIM + 1] = sqrtf(sd[0]);       // loss_o
        g_arr2 = 0;                                            // reset
    }
}

// ---------------- launch ----------------
extern "C" void kernel_launch(void* const* d_in, const int* in_sizes, int n_in,
                              void* d_out, int out_size) {
    const float* X     = (const float*)d_in[0];
    const float* A     = (const float*)d_in[1];
    const float* Wrel  = (const float*)d_in[2];
    const float* brel  = (const float*)d_in[3];
    const float* Wroot = (const float*)d_in[4];
    const float* Wmlp  = (const float*)d_in[5];
    const float* bmlp  = (const float*)d_in[6];
    float* out = (float*)d_out;

    cudaFuncSetAttribute(k4_yz, cudaFuncAttributeMaxDynamicSharedMemorySize, 98304);

    kA_stats<<<1024, 256>>>(X);
    kB_weights<<<65, 256>>>(Wrel, brel, Wroot, Wmlp, bmlp);
    k4_yz<<<256, 256, 98304>>>(X);
    k5_main<<<N_NODES, 256>>>(A, out);
    k6_pass2<<<N_NODES / 8, 256>>>();
    k7k8<<<256, 256>>>(out);
}

// round 5
// speedup vs baseline: 1.6456x; 1.0959x over previous
#include <cuda_runtime.h>
#include <cstdint>

// Problem constants
#define N_NODES 8192
#define T_DIM   256
#define F_DIM   128
#define C_DIM   32
#define NT_TOT  (N_NODES * T_DIM)   // 2097152
#define MAXDEG  512
#define LN_EPS  1e-5f

// ---------------- device scratch ----------------
__device__ float g_W1[C_DIM * T_DIM];     // W_mlp @ W_rel   [32,256]
__device__ float g_W2[C_DIM * T_DIM];     // W_mlp @ W_root  [32,256]
__device__ float g_bS[C_DIM];
__device__ float g_w1sum[C_DIM];
__device__ float g_w2sum[C_DIM];
__device__ float g_stats[2];              // mu, rstd
__device__ float g_part[2048];            // block partials for mean/var
__device__ int   g_arr1 = 0;              // arrival counter (stats)
__device__ int   g_arr2 = 0;              // arrival counter (k678)
__device__ float g_Y[N_NODES * C_DIM];    // Xn @ W1^T  [8192,32]
__device__ float g_Z[N_NODES * C_DIM];    // Xn @ W2^T + bS
__device__ int   g_nz[(size_t)N_NODES * MAXDEG];
__device__ int   g_cnt[N_NODES];
__device__ float g_dinv[N_NODES];
__device__ float g_s[N_NODES * C_DIM];    // softmax(S)
__device__ float g_rownum[N_NODES];
__device__ float g_rowden[N_NODES];
__device__ float g_sspart[1024 * C_DIM];  // partials for s^T s (per block)

// ---------------- kAB: fused X-stats + weight folding ----------------
// blocks [0,64): W1/W2 GEMM; block 64: bS/w1sum/w2sum; blocks [65,1089): X mean/var
__global__ void kAB(const float* __restrict__ X,
                    const float* __restrict__ Wrel,
                    const float* __restrict__ brel,
                    const float* __restrict__ Wroot,
                    const float* __restrict__ Wmlp,
                    const float* __restrict__ bmlp) {
    int tid = threadIdx.x;
    int b = blockIdx.x;

    if (b < 64) {
        int o = b * 256 + tid;              // < 16384
        int m = o >> 13;
        int r = o & 8191;
        int c = r >> 8;
        int t = r & 255;
        const float* Wx = m ? Wroot : Wrel;
        float acc = 0.f;
        #pragma unroll 8
        for (int f = 0; f < F_DIM; f++)
            acc += Wmlp[c * F_DIM + f] * Wx[f * T_DIM + t];
        if (m) g_W2[c * T_DIM + t] = acc;
        else   g_W1[c * T_DIM + t] = acc;
        return;
    }
    if (b == 64) {
        // rowsums of Wrel/Wroot, then tiny dots with Wmlp
        __shared__ float rs[256];           // [0:128) rs_rel, [128:256) rs_root
        __shared__ float WmT[128 * 33];     // transposed Wmlp, padded
        int lane = tid & 31, w = tid >> 5;
        for (int o = tid; o < 4096; o += 256) {
            int c = o >> 7, f = o & 127;
            WmT[f * 33 + c] = Wmlp[o];
        }
        const float* src = (w < 4) ? Wrel : Wroot;
        int rbase = (w & 3) * 32;
        for (int r = rbase; r < rbase + 32; r++) {
            float a = 0.f;
            for (int t2 = lane; t2 < T_DIM; t2 += 32) a += src[r * T_DIM + t2];
            for (int o = 16; o > 0; o >>= 1) a += __shfl_xor_sync(0xffffffffu, a, o);
            if (lane == 0) rs[(w < 4 ? 0 : 128) + r] = a;
        }
        __syncthreads();
        if (tid < 96) {
            int c = tid & 31, which = tid >> 5;   // 0: w1sum, 1: w2sum, 2: bS
            float a = 0.f;
            if (which == 2) {
                for (int f = 0; f < F_DIM; f++) a += WmT[f * 33 + c] * brel[f];
                g_bS[c] = a + bmlp[c];
            } else {
                const float* rsp = rs + which * 128;
                for (int f = 0; f < F_DIM; f++) a += WmT[f * 33 + c] * rsp[f];
                if (which) g_w2sum[c] = a; else g_w1sum[c] = a;
            }
        }
        return;
    }

    // ---- X mean/var: 1024 blocks, last-arrived finalizes ----
    int bid = b - 65;
    int g = bid * 256 + tid;
    float s = 0.f, q = 0.f;
    for (int k = g; k < NT_TOT; k += 1024 * 256) {
        float x = X[k];
        s += x; q += x * x;
    }
    __shared__ float ss[256], sq[256];
    ss[tid] = s; sq[tid] = q;
    __syncthreads();
    for (int o = 128; o > 0; o >>= 1) {
        if (tid < o) { ss[tid] += ss[tid + o]; sq[tid] += sq[tid + o]; }
        __syncthreads();
    }
    __shared__ bool isLast;
    if (tid == 0) {
        g_part[bid] = ss[0];
        g_part[1024 + bid] = sq[0];
        __threadfence();
        isLast = (atomicAdd(&g_arr1, 1) == 1023);
    }
    __syncthreads();
    if (!isLast) return;

    float a = 0.f, bb = 0.f;
    #pragma unroll
    for (int u = 0; u < 4; u++) {
        a  += g_part[tid * 4 + u];
        bb += g_part[1024 + tid * 4 + u];
    }
    ss[tid] = a; sq[tid] = bb;
    __syncthreads();
    for (int o = 128; o > 0; o >>= 1) {
        if (tid < o) { ss[tid] += ss[tid + o]; sq[tid] += sq[tid + o]; }
        __syncthreads();
    }
    if (tid == 0) {
        float mu = ss[0] / (float)NT_TOT;
        float var = sq[0] / (float)NT_TOT - mu * mu;
        g_stats[0] = mu;
        g_stats[1] = rsqrtf(var + LN_EPS);
        g_arr1 = 0;                       // reset for next replay
    }
}

// ---------------- K4: Y = Xn@W1^T, Z = Xn@W2^T + bS  (LN folded) ----------------
__global__ void k4_yz(const float* __restrict__ X) {
    extern __shared__ float sm[];
    float* W1s = sm;                 // [256*32] transposed: W1s[t*32+c]
    float* W2s = sm + 8192;
    float* Xs  = sm + 16384;         // 32 rows * 256
    int tid = threadIdx.x, lane = tid & 31, w = tid >> 5;

    for (int o = tid; o < 8192; o += 256) {
        int t = o >> 5, c = o & 31;
        W1s[o] = g_W1[c * T_DIM + t];
        W2s[o] = g_W2[c * T_DIM + t];
    }
    int rbase = blockIdx.x * 32;
    const float4* xsrc = (const float4*)(X + (size_t)rbase * T_DIM);
    float4* xd = (float4*)Xs;
    for (int o = tid; o < 2048; o += 256) xd[o] = xsrc[o];
    __syncthreads();

    float mu = g_stats[0], rstd = g_stats[1];
    float aY0 = 0, aY1 = 0, aY2 = 0, aY3 = 0;
    float aZ0 = 0, aZ1 = 0, aZ2 = 0, aZ3 = 0;
    const float* x0 = Xs + (w * 4 + 0) * 256;
    const float* x1 = Xs + (w * 4 + 1) * 256;
    const float* x2 = Xs + (w * 4 + 2) * 256;
    const float* x3 = Xs + (w * 4 + 3) * 256;
    #pragma unroll 4
    for (int t = 0; t < 256; t++) {
        float w1 = W1s[t * 32 + lane], w2 = W2s[t * 32 + lane];
        float xa = x0[t], xb = x1[t], xc = x2[t], xe = x3[t];
        aY0 += xa * w1; aZ0 += xa * w2;
        aY1 += xb * w1; aZ1 += xb * w2;
        aY2 += xc * w1; aZ2 += xc * w2;
        aY3 += xe * w1; aZ3 += xe * w2;
    }
    float c1 = mu * g_w1sum[lane];
    float c2 = mu * g_w2sum[lane];
    float bs = g_bS[lane];
    int r0 = rbase + w * 4;
    g_Y[(r0 + 0) * 32 + lane] = rstd * (aY0 - c1);
    g_Y[(r0 + 1) * 32 + lane] = rstd * (aY1 - c1);
    g_Y[(r0 + 2) * 32 + lane] = rstd * (aY2 - c1);
    g_Y[(r0 + 3) * 32 + lane] = rstd * (aY3 - c1);
    g_Z[(r0 + 0) * 32 + lane] = rstd * (aZ0 - c2) + bs;
    g_Z[(r0 + 1) * 32 + lane] = rstd * (aZ1 - c2) + bs;
    g_Z[(r0 + 2) * 32 + lane] = rstd * (aZ2 - c2) + bs;
    g_Z[(r0 + 3) * 32 + lane] = rstd * (aZ3 - c2) + bs;
}

// ---------------- K5a: stream A -> CSR + dinv (pure streaming) ----------------
__global__ void __launch_bounds__(256) k5a(const float* __restrict__ A) {
    int i = blockIdx.x;
    int tid = threadIdx.x, lane = tid & 31, wid = tid >> 5;
    __shared__ int s_warp[8];
    __shared__ int s_total;

    // A row = 2048 float4; chunk u covers [u*256, (u+1)*256), coalesced.
    const float4* arow = (const float4*)(A + (size_t)i * N_NODES);
    unsigned mask = 0;
    #pragma unroll
    for (int u = 0; u < 8; u++) {
        float4 v = arow[u * 256 + tid];
        unsigned bb = (v.x != 0.f) | ((v.y != 0.f) << 1) |
                      ((v.z != 0.f) << 2) | ((v.w != 0.f) << 3);
        mask |= bb << (u * 4);
    }
    int cntL = __popc(mask);

    // deterministic block scan of per-thread counts
    int incl = cntL;
    for (int o = 1; o < 32; o <<= 1) {
        int n = __shfl_up_sync(0xffffffffu, incl, o);
        if (lane >= o) incl += n;
    }
    if (lane == 31) s_warp[wid] = incl;
    __syncthreads();
    if (tid < 8) {
        int wv = s_warp[tid];
        int inc = wv;
        for (int o = 1; o < 8; o <<= 1) {
            int n = __shfl_up_sync(0xffu, inc, o);
            if (tid >= o) inc += n;
        }
        if (tid == 7) s_total = inc;
        s_warp[tid] = inc - wv;   // exclusive warp offset
    }
    __syncthreads();

    // emit directly to global CSR
    size_t rowbase = (size_t)i * MAXDEG;
    int p = s_warp[wid] + (incl - cntL);
    unsigned m = mask;
    while (m) {
        int bb = __ffs(m) - 1;
        m &= m - 1;
        // bit (u*4+q) -> column u*1024 + tid*4 + q
        int col = ((bb >> 2) << 10) + (tid << 2) + (bb & 3);
        if (p < MAXDEG) g_nz[rowbase + p++] = col;
    }
    if (tid == 0) {
        int total = s_total;
        if (total > MAXDEG) total = MAXDEG;
        g_cnt[i] = total;
        g_dinv[i] = rsqrtf((float)total);   // A is 0/1: degree == nnz
    }
}

// ---------------- K5b: gather + softmax (warp per row) ----------------
__global__ void __launch_bounds__(256) k5b(float* __restrict__ out) {
    int tid = threadIdx.x, lane = tid & 31, w = tid >> 5;
    int i = blockIdx.x * 8 + w;

    int cnt = g_cnt[i];
    const size_t base = (size_t)i * MAXDEG;
    float acc = 0.f;
    for (int kk = 0; kk < cnt; kk += 32) {
        int valid = (kk + lane) < cnt;
        int idx = valid ? g_nz[base + kk + lane] : 0;
        int mrem = cnt - kk; if (mrem > 32) mrem = 32;
        for (int e = 0; e < mrem; e++) {
            int j = __shfl_sync(0xffffffffu, idx, e);
            acc += g_Y[j * 32 + lane];      // coalesced 128B, L2-resident
        }
    }
    float Sv = acc + g_Z[i * 32 + lane];
    out[(size_t)i * 32 + lane] = Sv;        // output S

    float mx = Sv;
    for (int o = 16; o > 0; o >>= 1) mx = fmaxf(mx, __shfl_xor_sync(0xffffffffu, mx, o));
    float e = expf(Sv - mx);
    float ssum = e;
    for (int o = 16; o > 0; o >>= 1) ssum += __shfl_xor_sync(0xffffffffu, ssum, o);
    g_s[i * 32 + lane] = e / ssum;
}

// ---------------- K678: mincut row terms + s^T s partials + finalize ----------------
// 1024 blocks. Block b: mincut rows b*8+w (warp w), plus sTs slice (c1=b&31, chunk=b>>5).
__global__ void __launch_bounds__(256) k678(float* __restrict__ out) {
    int b = blockIdx.x;
    int tid = threadIdx.x, lane = tid & 31, w = tid >> 5;

    // ---- mincut part: row i ----
    int i = b * 8 + w;
    float si = g_s[i * 32 + lane];
    float nsq = si * si;
    for (int o = 16; o > 0; o >>= 1) nsq += __shfl_xor_sync(0xffffffffu, nsq, o);

    float di = g_dinv[i];
    int cnt = g_cnt[i];
    const size_t base = (size_t)i * MAXDEG;
    float accn = 0.f, accd = 0.f;
    for (int kk = 0; kk < cnt; kk += 32) {
        int valid = (kk + lane) < cnt;
        int idx = valid ? g_nz[base + kk + lane] : 0;
        float dv = valid ? g_dinv[idx] : 0.f;
        int mrem = cnt - kk; if (mrem > 32) mrem = 32;
        for (int e = 0; e < mrem; e++) {
            int j    = __shfl_sync(0xffffffffu, idx, e);
            float dj = __shfl_sync(0xffffffffu, dv, e);
            float sj = g_s[j * 32 + lane];
            accn += dj * si * sj;
        }
        float t = dv;
        for (int o = 16; o > 0; o >>= 1) t += __shfl_xor_sync(0xffffffffu, t, o);
        accd += t;
    }
    for (int o = 16; o > 0; o >>= 1) accn += __shfl_xor_sync(0xffffffffu, accn, o);
    if (lane == 0) {
        g_rownum[i] = di * accn;
        g_rowden[i] = di * accd * nsq;
    }

    // ---- sTs partial: (c1, chunk) slice over 256 rows ----
    int c1 = b & 31, chunk = b >> 5;
    float acc = 0.f;
    int iend = chunk * 256 + 256;
    for (int ii = chunk * 256 + w; ii < iend; ii += 8)
        acc += g_s[ii * 32 + c1] * g_s[ii * 32 + lane];
    __shared__ float red[256];
    red[tid] = acc;
    __syncthreads();
    for (int o = 128; o >= 32; o >>= 1) {
        if (tid < o) red[tid] += red[tid + o];
        __syncthreads();
    }
    if (tid < 32) g_sspart[b * 32 + tid] = red[tid];

    __shared__ bool isLast;
    if (tid == 0) {
        __threadfence();
        isLast = (atomicAdd(&g_arr2, 1) == 1023);
    }
    __syncthreads();
    if (!isLast) return;

    // ---- finalize losses (256 threads) ----
    __shared__ float sd[256];
    __shared__ float s_num, s_den, s_frob;

    float an = 0.f, ad = 0.f;
    for (int k = tid; k < N_NODES; k += 256) {
        an += g_rownum[k];
        ad += g_rowden[k];
    }
    sd[tid] = an;
    __syncthreads();
    for (int o = 128; o > 0; o >>= 1) { if (tid < o) sd[tid] += sd[tid + o]; __syncthreads(); }
    if (tid == 0) s_num = sd[0];
    __syncthreads();
    sd[tid] = ad;
    __syncthreads();
    for (int o = 128; o > 0; o >>= 1) { if (tid < o) sd[tid] += sd[tid + o]; __syncthreads(); }
    if (tid == 0) s_den = sd[0];
    __syncthreads();

    // each thread owns 4 entries of ss (1024 total); sum over 32 chunks each
    float ssv[4];
    float fr = 0.f;
    #pragma unroll
    for (int u = 0; u < 4; u++) {
        int e = tid * 4 + u;
        int e1 = e >> 5, e2 = e & 31;
        float v = 0.f;
        #pragma unroll
        for (int ch = 0; ch < 32; ch++)
            v += g_sspart[((ch << 5) | e1) * 32 + e2];
        ssv[u] = v;
        fr += v * v;
    }
    sd[tid] = fr;
    __syncthreads();
    for (int o = 128; o > 0; o >>= 1) { if (tid < o) sd[tid] += sd[tid + o]; __syncthreads(); }
    if (tid == 0) s_frob = sqrtf(sd[0]);
    __syncthreads();

    float dsum = 0.f;
    #pragma unroll
    for (int u = 0; u < 4; u++) {
        int e = tid * 4 + u;
        int e1 = e >> 5, e2 = e & 31;
        float diff = ssv[u] / s_frob - ((e1 == e2) ? rsqrtf((float)C_DIM) : 0.f);
        dsum += diff * diff;
    }
    sd[tid] = dsum;
    __syncthreads();
    for (int o = 128; o > 0; o >>= 1) { if (tid < o) sd[tid] += sd[tid + o]; __syncthreads(); }

    if (tid == 0) {
        out[(size_t)N_NODES * C_DIM + 0] = -(s_num / s_den);   // loss_mc
        out[(size_t)N_NODES * C_DIM + 1] = sqrtf(sd[0]);       // loss_o
        g_arr2 = 0;                                            // reset
    }
}

// ---------------- launch (fork/join: X-chain overlaps A-stream) ----------------
extern "C" void kernel_launch(void* const* d_in, const int* in_sizes, int n_in,
                              void* d_out, int out_size) {
    const float* X     = (const float*)d_in[0];
    const float* A     = (const float*)d_in[1];
    const float* Wrel  = (const float*)d_in[2];
    const float* brel  = (const float*)d_in[3];
    const float* Wroot = (const float*)d_in[4];
    const float* Wmlp  = (const float*)d_in[5];
    const float* bmlp  = (const float*)d_in[6];
    float* out = (float*)d_out;

    static cudaStream_t s1 = nullptr;
    static cudaEvent_t evF = nullptr, evJ = nullptr;
    if (s1 == nullptr) {
        cudaStreamCreateWithFlags(&s1, cudaStreamNonBlocking);
        cudaEventCreateWithFlags(&evF, cudaEventDisableTiming);
        cudaEventCreateWithFlags(&evJ, cudaEventDisableTiming);
        cudaFuncSetAttribute(k4_yz, cudaFuncAttributeMaxDynamicSharedMemorySize, 98304);
    }

    // fork: X-chain on s1, A-stream on the capture (legacy) stream
    cudaEventRecord(evF, 0);
    cudaStreamWaitEvent(s1, evF, 0);
    kAB<<<1089, 256, 0, s1>>>(X, Wrel, brel, Wroot, Wmlp, bmlp);
    k4_yz<<<256, 256, 98304, s1>>>(X);
    cudaEventRecord(evJ, s1);

    k5a<<<N_NODES, 256>>>(A);               // overlaps with s1 work

    // join: k5b needs g_Y/g_Z (s1) and CSR (k5a)
    cudaStreamWaitEvent((cudaStream_t)0, evJ, 0);
    k5b<<<N_NODES / 8, 256>>>(out);
    k678<<<1024, 256>>>(out);
}

// round 6
// speedup vs baseline: 2.0006x; 1.2157x over previous
#include <cuda_runtime.h>
#include <cstdint>

// Problem constants
#define N_NODES 8192
#define T_DIM   256
#define F_DIM   128
#define C_DIM   32
#define NT_TOT  (N_NODES * T_DIM)   // 2097152
#define MAXDEG  512
#define LN_EPS  1e-5f
#define WSTRIDE 260                  // padded [c][t] smem stride for k4

// ---------------- device scratch ----------------
__device__ float g_W1[C_DIM * T_DIM];     // W_mlp @ W_rel   [32,256]
__device__ float g_W2[C_DIM * T_DIM];     // W_mlp @ W_root  [32,256]
__device__ float g_bS[C_DIM];
__device__ float g_w1sum[C_DIM];
__device__ float g_w2sum[C_DIM];
__device__ float g_stats[2];              // mu, rstd
__device__ float g_part[2048];            // block partials for mean/var
__device__ int   g_arr1 = 0;              // arrival counter (stats)
__device__ int   g_arr2 = 0;              // arrival counter (k678)
__device__ float g_Y[N_NODES * C_DIM];    // Xn @ W1^T  [8192,32]
__device__ float g_Z[N_NODES * C_DIM];    // Xn @ W2^T + bS
__device__ int   g_nz[(size_t)N_NODES * MAXDEG];
__device__ int   g_cnt[N_NODES];
__device__ float g_dinv[N_NODES];
__device__ float g_s[N_NODES * C_DIM];    // softmax(S)
__device__ float g_rownum[N_NODES];
__device__ float g_rowden[N_NODES];
__device__ float g_sspart[1024 * C_DIM];  // partials for s^T s (per block)

// ---------------- kAB: fused X-stats + weight folding ----------------
// blocks [0,64): W1/W2 GEMM; block 64: bS/w1sum/w2sum; blocks [65,1089): X mean/var
__global__ void kAB(const float* __restrict__ X,
                    const float* __restrict__ Wrel,
                    const float* __restrict__ brel,
                    const float* __restrict__ Wroot,
                    const float* __restrict__ Wmlp,
                    const float* __restrict__ bmlp) {
    int tid = threadIdx.x;
    int b = blockIdx.x;

    if (b < 64) {
        int o = b * 256 + tid;              // < 16384
        int m = o >> 13;
        int r = o & 8191;
        int c = r >> 8;
        int t = r & 255;
        const float* Wx = m ? Wroot : Wrel;
        float acc = 0.f;
        #pragma unroll 8
        for (int f = 0; f < F_DIM; f++)
            acc += Wmlp[c * F_DIM + f] * Wx[f * T_DIM + t];
        if (m) g_W2[c * T_DIM + t] = acc;
        else   g_W1[c * T_DIM + t] = acc;
        return;
    }
    if (b == 64) {
        __shared__ float rs[256];           // [0:128) rs_rel, [128:256) rs_root
        __shared__ float WmT[128 * 33];     // transposed Wmlp, padded
        int lane = tid & 31, w = tid >> 5;
        for (int o = tid; o < 4096; o += 256) {
            int c = o >> 7, f = o & 127;
            WmT[f * 33 + c] = Wmlp[o];
        }
        const float* src = (w < 4) ? Wrel : Wroot;
        int rbase = (w & 3) * 32;
        for (int r = rbase; r < rbase + 32; r++) {
            float a = 0.f;
            for (int t2 = lane; t2 < T_DIM; t2 += 32) a += src[r * T_DIM + t2];
            for (int o = 16; o > 0; o >>= 1) a += __shfl_xor_sync(0xffffffffu, a, o);
            if (lane == 0) rs[(w < 4 ? 0 : 128) + r] = a;
        }
        __syncthreads();
        if (tid < 96) {
            int c = tid & 31, which = tid >> 5;   // 0: w1sum, 1: w2sum, 2: bS
            float a = 0.f;
            if (which == 2) {
                for (int f = 0; f < F_DIM; f++) a += WmT[f * 33 + c] * brel[f];
                g_bS[c] = a + bmlp[c];
            } else {
                const float* rsp = rs + which * 128;
                for (int f = 0; f < F_DIM; f++) a += WmT[f * 33 + c] * rsp[f];
                if (which) g_w2sum[c] = a; else g_w1sum[c] = a;
            }
        }
        return;
    }

    // ---- X mean/var ----
    int bid = b - 65;
    int g = bid * 256 + tid;
    float s = 0.f, q = 0.f;
    for (int k = g; k < NT_TOT; k += 1024 * 256) {
        float x = X[k];
        s += x; q += x * x;
    }
    __shared__ float ss[256], sq[256];
    ss[tid] = s; sq[tid] = q;
    __syncthreads();
    for (int o = 128; o > 0; o >>= 1) {
        if (tid < o) { ss[tid] += ss[tid + o]; sq[tid] += sq[tid + o]; }
        __syncthreads();
    }
    __shared__ bool isLast;
    if (tid == 0) {
        g_part[bid] = ss[0];
        g_part[1024 + bid] = sq[0];
        __threadfence();
        isLast = (atomicAdd(&g_arr1, 1) == 1023);
    }
    __syncthreads();
    if (!isLast) return;

    float a = 0.f, bb = 0.f;
    #pragma unroll
    for (int u = 0; u < 4; u++) {
        a  += g_part[tid * 4 + u];
        bb += g_part[1024 + tid * 4 + u];
    }
    ss[tid] = a; sq[tid] = bb;
    __syncthreads();
    for (int o = 128; o > 0; o >>= 1) {
        if (tid < o) { ss[tid] += ss[tid + o]; sq[tid] += sq[tid + o]; }
        __syncthreads();
    }
    if (tid == 0) {
        float mu = ss[0] / (float)NT_TOT;
        float var = sq[0] / (float)NT_TOT - mu * mu;
        g_stats[0] = mu;
        g_stats[1] = rsqrtf(var + LN_EPS);
        g_arr1 = 0;
    }
}

// ---------------- K4: Y = Xn@W1^T, Z = Xn@W2^T + bS (LN folded, float4 LDS) ----------------
__global__ void k4_yz(const float* __restrict__ X) {
    extern __shared__ float sm[];
    float* W1s = sm;                             // [32][WSTRIDE]  W1s[c*WSTRIDE + t]
    float* W2s = sm + 32 * WSTRIDE;
    float* Xs  = sm + 64 * WSTRIDE;              // 32 rows * 256
    int tid = threadIdx.x, lane = tid & 31, w = tid >> 5;

    for (int o = tid; o < 8192; o += 256) {
        int c = o >> 8, t = o & 255;
        W1s[c * WSTRIDE + t] = g_W1[o];
        W2s[c * WSTRIDE + t] = g_W2[o];
    }
    int rbase = blockIdx.x * 32;
    const float4* xsrc = (const float4*)(X + (size_t)rbase * T_DIM);
    float4* xd = (float4*)Xs;
    for (int o = tid; o < 2048; o += 256) xd[o] = xsrc[o];
    __syncthreads();

    float mu = g_stats[0], rstd = g_stats[1];
    float aY0 = 0, aY1 = 0, aY2 = 0, aY3 = 0;
    float aZ0 = 0, aZ1 = 0, aZ2 = 0, aZ3 = 0;
    const float* x0 = Xs + (w * 4 + 0) * 256;
    const float* x1 = Xs + (w * 4 + 1) * 256;
    const float* x2 = Xs + (w * 4 + 2) * 256;
    const float* x3 = Xs + (w * 4 + 3) * 256;
    const float* w1p = W1s + lane * WSTRIDE;
    const float* w2p = W2s + lane * WSTRIDE;
    #pragma unroll 4
    for (int t = 0; t < 256; t += 4) {
        float4 w1 = *(const float4*)(w1p + t);
        float4 w2 = *(const float4*)(w2p + t);
        float4 xa = *(const float4*)(x0 + t);
        float4 xb = *(const float4*)(x1 + t);
        float4 xc = *(const float4*)(x2 + t);
        float4 xe = *(const float4*)(x3 + t);
        aY0 += xa.x*w1.x + xa.y*w1.y + xa.z*w1.z + xa.w*w1.w;
        aZ0 += xa.x*w2.x + xa.y*w2.y + xa.z*w2.z + xa.w*w2.w;
        aY1 += xb.x*w1.x + xb.y*w1.y + xb.z*w1.z + xb.w*w1.w;
        aZ1 += xb.x*w2.x + xb.y*w2.y + xb.z*w2.z + xb.w*w2.w;
        aY2 += xc.x*w1.x + xc.y*w1.y + xc.z*w1.z + xc.w*w1.w;
        aZ2 += xc.x*w2.x + xc.y*w2.y + xc.z*w2.z + xc.w*w2.w;
        aY3 += xe.x*w1.x + xe.y*w1.y + xe.z*w1.z + xe.w*w1.w;
        aZ3 += xe.x*w2.x + xe.y*w2.y + xe.z*w2.z + xe.w*w2.w;
    }
    float c1 = mu * g_w1sum[lane];
    float c2 = mu * g_w2sum[lane];
    float bs = g_bS[lane];
    int r0 = rbase + w * 4;
    g_Y[(r0 + 0) * 32 + lane] = rstd * (aY0 - c1);
    g_Y[(r0 + 1) * 32 + lane] = rstd * (aY1 - c1);
    g_Y[(r0 + 2) * 32 + lane] = rstd * (aY2 - c1);
    g_Y[(r0 + 3) * 32 + lane] = rstd * (aY3 - c1);
    g_Z[(r0 + 0) * 32 + lane] = rstd * (aZ0 - c2) + bs;
    g_Z[(r0 + 1) * 32 + lane] = rstd * (aZ1 - c2) + bs;
    g_Z[(r0 + 2) * 32 + lane] = rstd * (aZ2 - c2) + bs;
    g_Z[(r0 + 3) * 32 + lane] = rstd * (aZ3 - c2) + bs;
}

// ---------------- K5a: stream A -> CSR + dinv ----------------
__global__ void __launch_bounds__(256) k5a(const float* __restrict__ A) {
    int i = blockIdx.x;
    int tid = threadIdx.x, lane = tid & 31, wid = tid >> 5;
    __shared__ int s_warp[8];
    __shared__ int s_total;

    const float4* arow = (const float4*)(A + (size_t)i * N_NODES);
    unsigned mask = 0;
    #pragma unroll
    for (int u = 0; u < 8; u++) {
        float4 v = arow[u * 256 + tid];
        unsigned bb = (v.x != 0.f) | ((v.y != 0.f) << 1) |
                      ((v.z != 0.f) << 2) | ((v.w != 0.f) << 3);
        mask |= bb << (u * 4);
    }
    int cntL = __popc(mask);

    int incl = cntL;
    for (int o = 1; o < 32; o <<= 1) {
        int n = __shfl_up_sync(0xffffffffu, incl, o);
        if (lane >= o) incl += n;
    }
    if (lane == 31) s_warp[wid] = incl;
    __syncthreads();
    if (tid < 8) {
        int wv = s_warp[tid];
        int inc = wv;
        for (int o = 1; o < 8; o <<= 1) {
            int n = __shfl_up_sync(0xffu, inc, o);
            if (tid >= o) inc += n;
        }
        if (tid == 7) s_total = inc;
        s_warp[tid] = inc - wv;
    }
    __syncthreads();

    size_t rowbase = (size_t)i * MAXDEG;
    int p = s_warp[wid] + (incl - cntL);
    unsigned m = mask;
    while (m) {
        int bb = __ffs(m) - 1;
        m &= m - 1;
        int col = ((bb >> 2) << 10) + (tid << 2) + (bb & 3);
        if (p < MAXDEG) g_nz[rowbase + p++] = col;
    }
    if (tid == 0) {
        int total = s_total;
        if (total > MAXDEG) total = MAXDEG;
        g_cnt[i] = total;
        g_dinv[i] = rsqrtf((float)total);   // A is 0/1: degree == nnz
    }
}

// ---------------- K5b: gather + softmax (4 edges in flight per warp) ----------------
__global__ void __launch_bounds__(256) k5b(float* __restrict__ out) {
    int tid = threadIdx.x, lane = tid & 31, w = tid >> 5;
    int i = blockIdx.x * 8 + w;
    int sub = lane >> 3;            // edge subgroup 0..3
    int ch4 = lane & 7;             // channel quad 0..7
    __shared__ float ex[8][32];

    int cnt = g_cnt[i];
    const size_t base = (size_t)i * MAXDEG;
    float4 acc = make_float4(0.f, 0.f, 0.f, 0.f);

    for (int kk = 0; kk < cnt; kk += 32) {
        int rem = cnt - kk; if (rem > 32) rem = 32;
        int idx = (kk + lane < cnt) ? g_nz[base + kk + lane] : 0;
        int ng = (rem + 3) >> 2;
        for (int g = 0; g < ng; g++) {
            int e = g * 4 + sub;
            int j = __shfl_sync(0xffffffffu, idx, e);
            float4 y = *(const float4*)(g_Y + j * 32 + ch4 * 4);
            if (e < rem) {
                acc.x += y.x; acc.y += y.y; acc.z += y.z; acc.w += y.w;
            }
        }
    }
    // combine the 4 edge subgroups (same channel quad)
    #pragma unroll
    for (int o = 8; o <= 16; o <<= 1) {
        acc.x += __shfl_xor_sync(0xffffffffu, acc.x, o);
        acc.y += __shfl_xor_sync(0xffffffffu, acc.y, o);
        acc.z += __shfl_xor_sync(0xffffffffu, acc.z, o);
        acc.w += __shfl_xor_sync(0xffffffffu, acc.w, o);
    }
    if (lane < 8) *(float4*)&ex[w][lane * 4] = acc;
    __syncwarp();

    float Sv = ex[w][lane] + g_Z[i * 32 + lane];
    out[(size_t)i * 32 + lane] = Sv;        // output S

    float mx = Sv;
    for (int o = 16; o > 0; o >>= 1) mx = fmaxf(mx, __shfl_xor_sync(0xffffffffu, mx, o));
    float e = expf(Sv - mx);
    float ssum = e;
    for (int o = 16; o > 0; o >>= 1) ssum += __shfl_xor_sync(0xffffffffu, ssum, o);
    g_s[i * 32 + lane] = e / ssum;
}

// ---------------- K678: mincut row terms + s^T s partials + finalize ----------------
__global__ void __launch_bounds__(256) k678(float* __restrict__ out) {
    int b = blockIdx.x;
    int tid = threadIdx.x, lane = tid & 31, w = tid >> 5;
    int sub = lane >> 3, ch4 = lane & 7;

    // ---- mincut part: row i, 4 edges in flight ----
    int i = b * 8 + w;
    float4 si4 = *(const float4*)(g_s + i * 32 + ch4 * 4);
    float nq = si4.x*si4.x + si4.y*si4.y + si4.z*si4.z + si4.w*si4.w;
    // lanes 0..7 of each subgroup span all 32 channels -> reduce bits 0..2
    #pragma unroll
    for (int o = 1; o <= 4; o <<= 1) nq += __shfl_xor_sync(0xffffffffu, nq, o);
    float nsq = nq;                 // uniform within each 8-lane group

    float di = g_dinv[i];
    int cnt = g_cnt[i];
    const size_t base = (size_t)i * MAXDEG;
    float4 accn = make_float4(0.f, 0.f, 0.f, 0.f);
    float accdL = 0.f;

    for (int kk = 0; kk < cnt; kk += 32) {
        int rem = cnt - kk; if (rem > 32) rem = 32;
        int valid = (kk + lane) < cnt;
        int idx = valid ? g_nz[base + kk + lane] : 0;
        float dv = valid ? g_dinv[idx] : 0.f;    // dv=0 masks invalid edges
        accdL += dv;
        int ng = (rem + 3) >> 2;
        for (int g = 0; g < ng; g++) {
            int e = g * 4 + sub;
            int j = __shfl_sync(0xffffffffu, idx, e);
            float dj = __shfl_sync(0xffffffffu, dv, e);   // 0 for invalid -> no predicate
            float4 sj = *(const float4*)(g_s + j * 32 + ch4 * 4);
            accn.x += dj * si4.x * sj.x;
            accn.y += dj * si4.y * sj.y;
            accn.z += dj * si4.z * sj.z;
            accn.w += dj * si4.w * sj.w;
        }
    }
    float an = accn.x + accn.y + accn.z + accn.w;   // each lane distinct (channel x subgroup)
    #pragma unroll
    for (int o = 16; o > 0; o >>= 1) an += __shfl_xor_sync(0xffffffffu, an, o);
    float ad = accdL;
    #pragma unroll
    for (int o = 16; o > 0; o >>= 1) ad += __shfl_xor_sync(0xffffffffu, ad, o);
    if (lane == 0) {
        g_rownum[i] = di * an;
        g_rowden[i] = di * ad * nsq;
    }

    // ---- sTs partial: (c1, chunk) slice over 256 rows ----
    int c1 = b & 31, chunk = b >> 5;
    float acc = 0.f;
    int iend = chunk * 256 + 256;
    for (int ii = chunk * 256 + w; ii < iend; ii += 8)
        acc += g_s[ii * 32 + c1] * g_s[ii * 32 + lane];
    __shared__ float red[256];
    red[tid] = acc;
    __syncthreads();
    for (int o = 128; o >= 32; o >>= 1) {
        if (tid < o) red[tid] += red[tid + o];
        __syncthreads();
    }
    if (tid < 32) g_sspart[b * 32 + tid] = red[tid];

    __shared__ bool isLast;
    if (tid == 0) {
        __threadfence();
        isLast = (atomicAdd(&g_arr2, 1) == 1023);
    }
    __syncthreads();
    if (!isLast) return;

    // ---- finalize losses ----
    __shared__ float sd[256];
    __shared__ float s_num, s_den, s_frob;

    float an2 = 0.f, ad2 = 0.f;
    for (int k = tid; k < N_NODES; k += 256) {
        an2 += g_rownum[k];
        ad2 += g_rowden[k];
    }
    sd[tid] = an2;
    __syncthreads();
    for (int o = 128; o > 0; o >>= 1) { if (tid < o) sd[tid] += sd[tid + o]; __syncthreads(); }
    if (tid == 0) s_num = sd[0];
    __syncthreads();
    sd[tid] = ad2;
    __syncthreads();
    for (int o = 128; o > 0; o >>= 1) { if (tid < o) sd[tid] += sd[tid + o]; __syncthreads(); }
    if (tid == 0) s_den = sd[0];
    __syncthreads();

    float ssv[4];
    float fr = 0.f;
    #pragma unroll
    for (int u = 0; u < 4; u++) {
        int e = tid * 4 + u;
        int e1 = e >> 5, e2 = e & 31;
        float v = 0.f;
        #pragma unroll
        for (int ch = 0; ch < 32; ch++)
            v += g_sspart[((ch << 5) | e1) * 32 + e2];
        ssv[u] = v;
        fr += v * v;
    }
    sd[tid] = fr;
    __syncthreads();
    for (int o = 128; o > 0; o >>= 1) { if (tid < o) sd[tid] += sd[tid + o]; __syncthreads(); }
    if (tid == 0) s_frob = sqrtf(sd[0]);
    __syncthreads();

    float dsum = 0.f;
    #pragma unroll
    for (int u = 0; u < 4; u++) {
        int e = tid * 4 + u;
        int e1 = e >> 5, e2 = e & 31;
        float diff = ssv[u] / s_frob - ((e1 == e2) ? rsqrtf((float)C_DIM) : 0.f);
        dsum += diff * diff;
    }
    sd[tid] = dsum;
    __syncthreads();
    for (int o = 128; o > 0; o >>= 1) { if (tid < o) sd[tid] += sd[tid + o]; __syncthreads(); }

    if (tid == 0) {
        out[(size_t)N_NODES * C_DIM + 0] = -(s_num / s_den);   // loss_mc
        out[(size_t)N_NODES * C_DIM + 1] = sqrtf(sd[0]);       // loss_o
        g_arr2 = 0;
    }
}

// ---------------- launch (fork/join: X-chain overlaps A-stream) ----------------
extern "C" void kernel_launch(void* const* d_in, const int* in_sizes, int n_in,
                              void* d_out, int out_size) {
    const float* X     = (const float*)d_in[0];
    const float* A     = (const float*)d_in[1];
    const float* Wrel  = (const float*)d_in[2];
    const float* brel  = (const float*)d_in[3];
    const float* Wroot = (const float*)d_in[4];
    const float* Wmlp  = (const float*)d_in[5];
    const float* bmlp  = (const float*)d_in[6];
    float* out = (float*)d_out;

    const int K4_SMEM = (64 * WSTRIDE + 8192) * 4;   // 99328 B

    static cudaStream_t s1 = nullptr;
    static cudaEvent_t evF = nullptr, evJ = nullptr;
    if (s1 == nullptr) {
        cudaStreamCreateWithFlags(&s1, cudaStreamNonBlocking);
        cudaEventCreateWithFlags(&evF, cudaEventDisableTiming);
        cudaEventCreateWithFlags(&evJ, cudaEventDisableTiming);
        cudaFuncSetAttribute(k4_yz, cudaFuncAttributeMaxDynamicSharedMemorySize, K4_SMEM);
    }

    // fork: X-chain on s1, A-stream on the capture stream
    cudaEventRecord(evF, 0);
    cudaStreamWaitEvent(s1, evF, 0);
    kAB<<<1089, 256, 0, s1>>>(X, Wrel, brel, Wroot, Wmlp, bmlp);
    k4_yz<<<256, 256, K4_SMEM, s1>>>(X);
    cudaEventRecord(evJ, s1);

    k5a<<<N_NODES, 256>>>(A);               // overlaps with s1 work

    // join: k5b needs g_Y/g_Z (s1) and CSR (k5a)
    cudaStreamWaitEvent((cudaStream_t)0, evJ, 0);
    k5b<<<N_NODES / 8, 256>>>(out);
    k678<<<1024, 256>>>(out);
}

// round 7
// speedup vs baseline: 2.1528x; 1.0761x over previous
#include <cuda_runtime.h>
#include <cstdint>

// Problem constants
#define N_NODES 8192
#define T_DIM   256
#define F_DIM   128
#define C_DIM   32
#define NT_TOT  (N_NODES * T_DIM)   // 2097152
#define MAXDEG  512
#define LN_EPS  1e-5f
#define WSTRIDE 260                  // padded [c][t] smem stride for k4

// ---------------- device scratch ----------------
__device__ float g_W1[C_DIM * T_DIM];     // W_mlp @ W_rel   [32,256]
__device__ float g_W2[C_DIM * T_DIM];     // W_mlp @ W_root  [32,256]
__device__ float g_bS[C_DIM];
__device__ float g_w1sum[C_DIM];
__device__ float g_w2sum[C_DIM];
__device__ float g_stats[2];              // mu, rstd
__device__ float g_part[2048];            // block partials for mean/var
__device__ int   g_arr1 = 0;              // arrival counter (stats)
__device__ int   g_arr2 = 0;              // arrival counter (k678)
__device__ float g_Y[N_NODES * C_DIM];    // Xn @ W1^T  [8192,32]
__device__ float g_Z[N_NODES * C_DIM];    // Xn @ W2^T + bS
__device__ int   g_nz[(size_t)N_NODES * MAXDEG];
__device__ int   g_cnt[N_NODES];
__device__ float g_dinv[N_NODES];
__device__ float g_s[N_NODES * C_DIM];    // softmax(S)
__device__ float g_rownum[N_NODES];
__device__ float g_rowden[N_NODES];
__device__ float g_sspart[1024 * C_DIM];  // partials for s^T s (per block)

// ---------------- kAB: fused X-stats + weight folding ----------------
__global__ void kAB(const float* __restrict__ X,
                    const float* __restrict__ Wrel,
                    const float* __restrict__ brel,
                    const float* __restrict__ Wroot,
                    const float* __restrict__ Wmlp,
                    const float* __restrict__ bmlp) {
    int tid = threadIdx.x;
    int b = blockIdx.x;

    if (b < 64) {
        int o = b * 256 + tid;              // < 16384
        int m = o >> 13;
        int r = o & 8191;
        int c = r >> 8;
        int t = r & 255;
        const float* Wx = m ? Wroot : Wrel;
        float acc = 0.f;
        #pragma unroll 8
        for (int f = 0; f < F_DIM; f++)
            acc += Wmlp[c * F_DIM + f] * Wx[f * T_DIM + t];
        if (m) g_W2[c * T_DIM + t] = acc;
        else   g_W1[c * T_DIM + t] = acc;
        return;
    }
    if (b == 64) {
        __shared__ float rs[256];           // [0:128) rs_rel, [128:256) rs_root
        __shared__ float WmT[128 * 33];     // transposed Wmlp, padded
        int lane = tid & 31, w = tid >> 5;
        for (int o = tid; o < 4096; o += 256) {
            int c = o >> 7, f = o & 127;
            WmT[f * 33 + c] = Wmlp[o];
        }
        const float* src = (w < 4) ? Wrel : Wroot;
        int rbase = (w & 3) * 32;
        for (int r = rbase; r < rbase + 32; r++) {
            float a = 0.f;
            for (int t2 = lane; t2 < T_DIM; t2 += 32) a += src[r * T_DIM + t2];
            for (int o = 16; o > 0; o >>= 1) a += __shfl_xor_sync(0xffffffffu, a, o);
            if (lane == 0) rs[(w < 4 ? 0 : 128) + r] = a;
        }
        __syncthreads();
        if (tid < 96) {
            int c = tid & 31, which = tid >> 5;   // 0: w1sum, 1: w2sum, 2: bS
            float a = 0.f;
            if (which == 2) {
                for (int f = 0; f < F_DIM; f++) a += WmT[f * 33 + c] * brel[f];
                g_bS[c] = a + bmlp[c];
            } else {
                const float* rsp = rs + which * 128;
                for (int f = 0; f < F_DIM; f++) a += WmT[f * 33 + c] * rsp[f];
                if (which) g_w2sum[c] = a; else g_w1sum[c] = a;
            }
        }
        return;
    }

    // ---- X mean/var ----
    int bid = b - 65;
    int g = bid * 256 + tid;
    float s = 0.f, q = 0.f;
    for (int k = g; k < NT_TOT; k += 1024 * 256) {
        float x = X[k];
        s += x; q += x * x;
    }
    __shared__ float ss[256], sq[256];
    ss[tid] = s; sq[tid] = q;
    __syncthreads();
    for (int o = 128; o > 0; o >>= 1) {
        if (tid < o) { ss[tid] += ss[tid + o]; sq[tid] += sq[tid + o]; }
        __syncthreads();
    }
    __shared__ bool isLast;
    if (tid == 0) {
        g_part[bid] = ss[0];
        g_part[1024 + bid] = sq[0];
        __threadfence();
        isLast = (atomicAdd(&g_arr1, 1) == 1023);
    }
    __syncthreads();
    if (!isLast) return;

    float a = 0.f, bb = 0.f;
    #pragma unroll
    for (int u = 0; u < 4; u++) {
        a  += g_part[tid * 4 + u];
        bb += g_part[1024 + tid * 4 + u];
    }
    ss[tid] = a; sq[tid] = bb;
    __syncthreads();
    for (int o = 128; o > 0; o >>= 1) {
        if (tid < o) { ss[tid] += ss[tid + o]; sq[tid] += sq[tid + o]; }
        __syncthreads();
    }
    if (tid == 0) {
        float mu = ss[0] / (float)NT_TOT;
        float var = sq[0] / (float)NT_TOT - mu * mu;
        g_stats[0] = mu;
        g_stats[1] = rsqrtf(var + LN_EPS);
        g_arr1 = 0;
    }
}

// ---------------- K4: Y = Xn@W1^T, Z = Xn@W2^T + bS (LN folded, float4 LDS) ----------------
__global__ void k4_yz(const float* __restrict__ X) {
    extern __shared__ float sm[];
    float* W1s = sm;                             // [32][WSTRIDE]
    float* W2s = sm + 32 * WSTRIDE;
    float* Xs  = sm + 64 * WSTRIDE;              // 32 rows * 256
    int tid = threadIdx.x, lane = tid & 31, w = tid >> 5;

    for (int o = tid; o < 8192; o += 256) {
        int c = o >> 8, t = o & 255;
        W1s[c * WSTRIDE + t] = g_W1[o];
        W2s[c * WSTRIDE + t] = g_W2[o];
    }
    int rbase = blockIdx.x * 32;
    const float4* xsrc = (const float4*)(X + (size_t)rbase * T_DIM);
    float4* xd = (float4*)Xs;
    for (int o = tid; o < 2048; o += 256) xd[o] = xsrc[o];
    __syncthreads();

    float mu = g_stats[0], rstd = g_stats[1];
    float aY0 = 0, aY1 = 0, aY2 = 0, aY3 = 0;
    float aZ0 = 0, aZ1 = 0, aZ2 = 0, aZ3 = 0;
    const float* x0 = Xs + (w * 4 + 0) * 256;
    const float* x1 = Xs + (w * 4 + 1) * 256;
    const float* x2 = Xs + (w * 4 + 2) * 256;
    const float* x3 = Xs + (w * 4 + 3) * 256;
    const float* w1p = W1s + lane * WSTRIDE;
    const float* w2p = W2s + lane * WSTRIDE;
    #pragma unroll 4
    for (int t = 0; t < 256; t += 4) {
        float4 w1 = *(const float4*)(w1p + t);
        float4 w2 = *(const float4*)(w2p + t);
        float4 xa = *(const float4*)(x0 + t);
        float4 xb = *(const float4*)(x1 + t);
        float4 xc = *(const float4*)(x2 + t);
        float4 xe = *(const float4*)(x3 + t);
        aY0 += xa.x*w1.x + xa.y*w1.y + xa.z*w1.z + xa.w*w1.w;
        aZ0 += xa.x*w2.x + xa.y*w2.y + xa.z*w2.z + xa.w*w2.w;
        aY1 += xb.x*w1.x + xb.y*w1.y + xb.z*w1.z + xb.w*w1.w;
        aZ1 += xb.x*w2.x + xb.y*w2.y + xb.z*w2.z + xb.w*w2.w;
        aY2 += xc.x*w1.x + xc.y*w1.y + xc.z*w1.z + xc.w*w1.w;
        aZ2 += xc.x*w2.x + xc.y*w2.y + xc.z*w2.z + xc.w*w2.w;
        aY3 += xe.x*w1.x + xe.y*w1.y + xe.z*w1.z + xe.w*w1.w;
        aZ3 += xe.x*w2.x + xe.y*w2.y + xe.z*w2.z + xe.w*w2.w;
    }
    float c1 = mu * g_w1sum[lane];
    float c2 = mu * g_w2sum[lane];
    float bs = g_bS[lane];
    int r0 = rbase + w * 4;
    g_Y[(r0 + 0) * 32 + lane] = rstd * (aY0 - c1);
    g_Y[(r0 + 1) * 32 + lane] = rstd * (aY1 - c1);
    g_Y[(r0 + 2) * 32 + lane] = rstd * (aY2 - c1);
    g_Y[(r0 + 3) * 32 + lane] = rstd * (aY3 - c1);
    g_Z[(r0 + 0) * 32 + lane] = rstd * (aZ0 - c2) + bs;
    g_Z[(r0 + 1) * 32 + lane] = rstd * (aZ1 - c2) + bs;
    g_Z[(r0 + 2) * 32 + lane] = rstd * (aZ2 - c2) + bs;
    g_Z[(r0 + 3) * 32 + lane] = rstd * (aZ3 - c2) + bs;
}

// ---------------- K5a: stream A -> CSR + dinv (streaming loads) ----------------
__global__ void __launch_bounds__(256) k5a(const float* __restrict__ A) {
    int i = blockIdx.x;
    int tid = threadIdx.x, lane = tid & 31, wid = tid >> 5;
    __shared__ int s_warp[8];
    __shared__ int s_total;

    const float4* arow = (const float4*)(A + (size_t)i * N_NODES);
    unsigned mask = 0;
    #pragma unroll
    for (int u = 0; u < 8; u++) {
        float4 v = __ldcs(&arow[u * 256 + tid]);   // streaming, evict-first
        unsigned bb = (v.x != 0.f) | ((v.y != 0.f) << 1) |
                      ((v.z != 0.f) << 2) | ((v.w != 0.f) << 3);
        mask |= bb << (u * 4);
    }
    int cntL = __popc(mask);

    int incl = cntL;
    for (int o = 1; o < 32; o <<= 1) {
        int n = __shfl_up_sync(0xffffffffu, incl, o);
        if (lane >= o) incl += n;
    }
    if (lane == 31) s_warp[wid] = incl;
    __syncthreads();
    if (tid < 8) {
        int wv = s_warp[tid];
        int inc = wv;
        for (int o = 1; o < 8; o <<= 1) {
            int n = __shfl_up_sync(0xffu, inc, o);
            if (tid >= o) inc += n;
        }
        if (tid == 7) s_total = inc;
        s_warp[tid] = inc - wv;
    }
    __syncthreads();

    size_t rowbase = (size_t)i * MAXDEG;
    int p = s_warp[wid] + (incl - cntL);
    unsigned m = mask;
    while (m) {
        int bb = __ffs(m) - 1;
        m &= m - 1;
        int col = ((bb >> 2) << 10) + (tid << 2) + (bb & 3);
        if (p < MAXDEG) g_nz[rowbase + p++] = col;
    }
    if (tid == 0) {
        int total = s_total;
        if (total > MAXDEG) total = MAXDEG;
        g_cnt[i] = total;
        g_dinv[i] = rsqrtf((float)total);   // A is 0/1: degree == nnz
    }
}

// ---------------- K5b: gather + softmax (lane=channel, 4-deep ILP) ----------------
__global__ void __launch_bounds__(256) k5b(float* __restrict__ out) {
    int tid = threadIdx.x, lane = tid & 31, w = tid >> 5;
    int i = blockIdx.x * 8 + w;

    int cnt = g_cnt[i];
    const size_t base = (size_t)i * MAXDEG;
    float a0 = 0.f, a1 = 0.f, a2 = 0.f, a3 = 0.f;

    for (int kk = 0; kk < cnt; kk += 32) {
        int rem = cnt - kk; if (rem > 32) rem = 32;
        int idx = (kk + lane < cnt) ? g_nz[base + kk + lane] : 0;
        int g = 0;
        for (; g + 4 <= rem; g += 4) {
            int j0 = __shfl_sync(0xffffffffu, idx, g + 0);
            int j1 = __shfl_sync(0xffffffffu, idx, g + 1);
            int j2 = __shfl_sync(0xffffffffu, idx, g + 2);
            int j3 = __shfl_sync(0xffffffffu, idx, g + 3);
            a0 += g_Y[j0 * 32 + lane];
            a1 += g_Y[j1 * 32 + lane];
            a2 += g_Y[j2 * 32 + lane];
            a3 += g_Y[j3 * 32 + lane];
        }
        for (; g < rem; g++) {
            int j = __shfl_sync(0xffffffffu, idx, g);
            a0 += g_Y[j * 32 + lane];
        }
    }
    float Sv = ((a0 + a1) + (a2 + a3)) + g_Z[i * 32 + lane];
    out[(size_t)i * 32 + lane] = Sv;        // output S

    float mx = Sv;
    for (int o = 16; o > 0; o >>= 1) mx = fmaxf(mx, __shfl_xor_sync(0xffffffffu, mx, o));
    float e = expf(Sv - mx);
    float ssum = e;
    for (int o = 16; o > 0; o >>= 1) ssum += __shfl_xor_sync(0xffffffffu, ssum, o);
    g_s[i * 32 + lane] = e / ssum;
}

// ---------------- K678: mincut row terms + s^T s partials + finalize ----------------
__global__ void __launch_bounds__(256) k678(float* __restrict__ out) {
    int b = blockIdx.x;
    int tid = threadIdx.x, lane = tid & 31, w = tid >> 5;

    // ---- mincut part: row i (lane=channel, 4-deep ILP) ----
    int i = b * 8 + w;
    float si = g_s[i * 32 + lane];
    float nsq = si * si;
    #pragma unroll
    for (int o = 16; o > 0; o >>= 1) nsq += __shfl_xor_sync(0xffffffffu, nsq, o);

    float di = g_dinv[i];
    int cnt = g_cnt[i];
    const size_t base = (size_t)i * MAXDEG;
    float n0 = 0.f, n1 = 0.f, n2 = 0.f, n3 = 0.f;
    float accdL = 0.f;

    for (int kk = 0; kk < cnt; kk += 32) {
        int rem = cnt - kk; if (rem > 32) rem = 32;
        int valid = (kk + lane) < cnt;
        int idx = valid ? g_nz[base + kk + lane] : 0;
        float dv = valid ? g_dinv[idx] : 0.f;
        accdL += dv;
        int g = 0;
        for (; g + 4 <= rem; g += 4) {
            int   j0 = __shfl_sync(0xffffffffu, idx, g + 0);
            int   j1 = __shfl_sync(0xffffffffu, idx, g + 1);
            int   j2 = __shfl_sync(0xffffffffu, idx, g + 2);
            int   j3 = __shfl_sync(0xffffffffu, idx, g + 3);
            float d0 = __shfl_sync(0xffffffffu, dv, g + 0);
            float d1 = __shfl_sync(0xffffffffu, dv, g + 1);
            float d2 = __shfl_sync(0xffffffffu, dv, g + 2);
            float d3 = __shfl_sync(0xffffffffu, dv, g + 3);
            n0 += d0 * g_s[j0 * 32 + lane];
            n1 += d1 * g_s[j1 * 32 + lane];
            n2 += d2 * g_s[j2 * 32 + lane];
            n3 += d3 * g_s[j3 * 32 + lane];
        }
        for (; g < rem; g++) {
            int   j = __shfl_sync(0xffffffffu, idx, g);
            float d = __shfl_sync(0xffffffffu, dv, g);
            n0 += d * g_s[j * 32 + lane];
        }
    }
    float an = si * (((n0 + n1) + (n2 + n3)));
    #pragma unroll
    for (int o = 16; o > 0; o >>= 1) an += __shfl_xor_sync(0xffffffffu, an, o);
    float ad = accdL;
    #pragma unroll
    for (int o = 16; o > 0; o >>= 1) ad += __shfl_xor_sync(0xffffffffu, ad, o);
    if (lane == 0) {
        g_rownum[i] = di * an;
        g_rowden[i] = di * ad * nsq;
    }

    // ---- sTs partial: (c1, chunk) slice over 256 rows ----
    int c1 = b & 31, chunk = b >> 5;
    float acc = 0.f;
    int iend = chunk * 256 + 256;
    for (int ii = chunk * 256 + w; ii < iend; ii += 8)
        acc += g_s[ii * 32 + c1] * g_s[ii * 32 + lane];
    __shared__ float red[256];
    red[tid] = acc;
    __syncthreads();
    for (int o = 128; o >= 32; o >>= 1) {
        if (tid < o) red[tid] += red[tid + o];
        __syncthreads();
    }
    if (tid < 32) g_sspart[b * 32 + tid] = red[tid];

    __shared__ bool isLast;
    if (tid == 0) {
        __threadfence();
        isLast = (atomicAdd(&g_arr2, 1) == 1023);
    }
    __syncthreads();
    if (!isLast) return;

    // ---- finalize losses ----
    __shared__ float sd[256];
    __shared__ float s_num, s_den, s_frob;

    float an2 = 0.f, ad2 = 0.f;
    for (int k = tid; k < N_NODES; k += 256) {
        an2 += g_rownum[k];
        ad2 += g_rowden[k];
    }
    sd[tid] = an2;
    __syncthreads();
    for (int o = 128; o > 0; o >>= 1) { if (tid < o) sd[tid] += sd[tid + o]; __syncthreads(); }
    if (tid == 0) s_num = sd[0];
    __syncthreads();
    sd[tid] = ad2;
    __syncthreads();
    for (int o = 128; o > 0; o >>= 1) { if (tid < o) sd[tid] += sd[tid + o]; __syncthreads(); }
    if (tid == 0) s_den = sd[0];
    __syncthreads();

    float ssv[4];
    float fr = 0.f;
    #pragma unroll
    for (int u = 0; u < 4; u++) {
        int e = tid * 4 + u;
        int e1 = e >> 5, e2 = e & 31;
        float v = 0.f;
        #pragma unroll
        for (int ch = 0; ch < 32; ch++)
            v += g_sspart[((ch << 5) | e1) * 32 + e2];
        ssv[u] = v;
        fr += v * v;
    }
    sd[tid] = fr;
    __syncthreads();
    for (int o = 128; o > 0; o >>= 1) { if (tid < o) sd[tid] += sd[tid + o]; __syncthreads(); }
    if (tid == 0) s_frob = sqrtf(sd[0]);
    __syncthreads();

    float dsum = 0.f;
    #pragma unroll
    for (int u = 0; u < 4; u++) {
        int e = tid * 4 + u;
        int e1 = e >> 5, e2 = e & 31;
        float diff = ssv[u] / s_frob - ((e1 == e2) ? rsqrtf((float)C_DIM) : 0.f);
        dsum += diff * diff;
    }
    sd[tid] = dsum;
    __syncthreads();
    for (int o = 128; o > 0; o >>= 1) { if (tid < o) sd[tid] += sd[tid + o]; __syncthreads(); }

    if (tid == 0) {
        out[(size_t)N_NODES * C_DIM + 0] = -(s_num / s_den);   // loss_mc
        out[(size_t)N_NODES * C_DIM + 1] = sqrtf(sd[0]);       // loss_o
        g_arr2 = 0;
    }
}

// ---------------- launch (fork/join: X-chain overlaps A-stream) ----------------
extern "C" void kernel_launch(void* const* d_in, const int* in_sizes, int n_in,
                              void* d_out, int out_size) {
    const float* X     = (const float*)d_in[0];
    const float* A     = (const float*)d_in[1];
    const float* Wrel  = (const float*)d_in[2];
    const float* brel  = (const float*)d_in[3];
    const float* Wroot = (const float*)d_in[4];
    const float* Wmlp  = (const float*)d_in[5];
    const float* bmlp  = (const float*)d_in[6];
    float* out = (float*)d_out;

    const int K4_SMEM = (64 * WSTRIDE + 8192) * 4;   // 99328 B

    static cudaStream_t s1 = nullptr;
    static cudaEvent_t evF = nullptr, evJ = nullptr;
    if (s1 == nullptr) {
        cudaStreamCreateWithFlags(&s1, cudaStreamNonBlocking);
        cudaEventCreateWithFlags(&evF, cudaEventDisableTiming);
        cudaEventCreateWithFlags(&evJ, cudaEventDisableTiming);
        cudaFuncSetAttribute(k4_yz, cudaFuncAttributeMaxDynamicSharedMemorySize, K4_SMEM);
    }

    // fork: X-chain on s1, A-stream on the capture stream
    cudaEventRecord(evF, 0);
    cudaStreamWaitEvent(s1, evF, 0);
    kAB<<<1089, 256, 0, s1>>>(X, Wrel, brel, Wroot, Wmlp, bmlp);
    k4_yz<<<256, 256, K4_SMEM, s1>>>(X);
    cudaEventRecord(evJ, s1);

    k5a<<<N_NODES, 256>>>(A);               // overlaps with s1 work

    // join: k5b needs g_Y/g_Z (s1) and CSR (k5a)
    cudaStreamWaitEvent((cudaStream_t)0, evJ, 0);
    k5b<<<N_NODES / 8, 256>>>(out);
    k678<<<1024, 256>>>(out);
}

// round 8
// speedup vs baseline: 2.1642x; 1.0053x over previous
#include <cuda_runtime.h>
#include <cstdint>

// Problem constants
#define N_NODES 8192
#define T_DIM   256
#define F_DIM   128
#define C_DIM   32
#define NT_TOT  (N_NODES * T_DIM)   // 2097152
#define MAXDEG  512
#define LN_EPS  1e-5f
#define WSTRIDE 260                  // padded [c][t] smem stride for k4

// ---------------- device scratch ----------------
__device__ float g_W1[C_DIM * T_DIM];     // W_mlp @ W_rel   [32,256]
__device__ float g_W2[C_DIM * T_DIM];     // W_mlp @ W_root  [32,256]
__device__ float g_bS[C_DIM];
__device__ float g_w1sum[C_DIM];
__device__ float g_w2sum[C_DIM];
__device__ float g_stats[2];              // mu, rstd
__device__ float g_part[2048];            // block partials for mean/var
__device__ int   g_arr1 = 0;              // arrival counter (stats)
__device__ int   g_arr2 = 0;              // arrival counter (k678)
__device__ float g_Y[N_NODES * C_DIM];    // Xn @ W1^T  [8192,32]
__device__ float g_Z[N_NODES * C_DIM];    // Xn @ W2^T + bS
__device__ int   g_nz[(size_t)N_NODES * MAXDEG];
__device__ int   g_cnt[N_NODES];
__device__ float g_dinv[N_NODES];
__device__ float g_s[N_NODES * C_DIM];    // softmax(S)
__device__ float g_w[N_NODES * C_DIM];    // dinv_j * s_j
__device__ float g_rownum[N_NODES];
__device__ float g_rowden[N_NODES];
__device__ float g_sspart[1024 * C_DIM];  // partials for s^T s (per block)

// ---------------- kAB: fused X-stats + weight folding ----------------
__global__ void kAB(const float* __restrict__ X,
                    const float* __restrict__ Wrel,
                    const float* __restrict__ brel,
                    const float* __restrict__ Wroot,
                    const float* __restrict__ Wmlp,
                    const float* __restrict__ bmlp) {
    int tid = threadIdx.x;
    int b = blockIdx.x;

    if (b < 64) {
        int o = b * 256 + tid;              // < 16384
        int m = o >> 13;
        int r = o & 8191;
        int c = r >> 8;
        int t = r & 255;
        const float* Wx = m ? Wroot : Wrel;
        float acc = 0.f;
        #pragma unroll 8
        for (int f = 0; f < F_DIM; f++)
            acc += Wmlp[c * F_DIM + f] * Wx[f * T_DIM + t];
        if (m) g_W2[c * T_DIM + t] = acc;
        else   g_W1[c * T_DIM + t] = acc;
        return;
    }
    if (b == 64) {
        __shared__ float rs[256];           // [0:128) rs_rel, [128:256) rs_root
        __shared__ float WmT[128 * 33];     // transposed Wmlp, padded
        int lane = tid & 31, w = tid >> 5;
        for (int o = tid; o < 4096; o += 256) {
            int c = o >> 7, f = o & 127;
            WmT[f * 33 + c] = Wmlp[o];
        }
        const float* src = (w < 4) ? Wrel : Wroot;
        int rbase = (w & 3) * 32;
        for (int r = rbase; r < rbase + 32; r++) {
            float a = 0.f;
            for (int t2 = lane; t2 < T_DIM; t2 += 32) a += src[r * T_DIM + t2];
            for (int o = 16; o > 0; o >>= 1) a += __shfl_xor_sync(0xffffffffu, a, o);
            if (lane == 0) rs[(w < 4 ? 0 : 128) + r] = a;
        }
        __syncthreads();
        if (tid < 96) {
            int c = tid & 31, which = tid >> 5;   // 0: w1sum, 1: w2sum, 2: bS
            float a = 0.f;
            if (which == 2) {
                for (int f = 0; f < F_DIM; f++) a += WmT[f * 33 + c] * brel[f];
                g_bS[c] = a + bmlp[c];
            } else {
                const float* rsp = rs + which * 128;
                for (int f = 0; f < F_DIM; f++) a += WmT[f * 33 + c] * rsp[f];
                if (which) g_w2sum[c] = a; else g_w1sum[c] = a;
            }
        }
        return;
    }

    // ---- X mean/var ----
    int bid = b - 65;
    int g = bid * 256 + tid;
    float s = 0.f, q = 0.f;
    for (int k = g; k < NT_TOT; k += 1024 * 256) {
        float x = X[k];
        s += x; q += x * x;
    }
    __shared__ float ss[256], sq[256];
    ss[tid] = s; sq[tid] = q;
    __syncthreads();
    for (int o = 128; o > 0; o >>= 1) {
        if (tid < o) { ss[tid] += ss[tid + o]; sq[tid] += sq[tid + o]; }
        __syncthreads();
    }
    __shared__ bool isLast;
    if (tid == 0) {
        g_part[bid] = ss[0];
        g_part[1024 + bid] = sq[0];
        __threadfence();
        isLast = (atomicAdd(&g_arr1, 1) == 1023);
    }
    __syncthreads();
    if (!isLast) return;

    float a = 0.f, bb = 0.f;
    #pragma unroll
    for (int u = 0; u < 4; u++) {
        a  += g_part[tid * 4 + u];
        bb += g_part[1024 + tid * 4 + u];
    }
    ss[tid] = a; sq[tid] = bb;
    __syncthreads();
    for (int o = 128; o > 0; o >>= 1) {
        if (tid < o) { ss[tid] += ss[tid + o]; sq[tid] += sq[tid + o]; }
        __syncthreads();
    }
    if (tid == 0) {
        float mu = ss[0] / (float)NT_TOT;
        float var = sq[0] / (float)NT_TOT - mu * mu;
        g_stats[0] = mu;
        g_stats[1] = rsqrtf(var + LN_EPS);
        g_arr1 = 0;
    }
}

// ---------------- K4: Y = Xn@W1^T, Z = Xn@W2^T + bS (LN folded, float4 LDS) ----------------
__global__ void k4_yz(const float* __restrict__ X) {
    extern __shared__ float sm[];
    float* W1s = sm;                             // [32][WSTRIDE]
    float* W2s = sm + 32 * WSTRIDE;
    float* Xs  = sm + 64 * WSTRIDE;              // 32 rows * 256
    int tid = threadIdx.x, lane = tid & 31, w = tid >> 5;

    for (int o = tid; o < 8192; o += 256) {
        int c = o >> 8, t = o & 255;
        W1s[c * WSTRIDE + t] = g_W1[o];
        W2s[c * WSTRIDE + t] = g_W2[o];
    }
    int rbase = blockIdx.x * 32;
    const float4* xsrc = (const float4*)(X + (size_t)rbase * T_DIM);
    float4* xd = (float4*)Xs;
    for (int o = tid; o < 2048; o += 256) xd[o] = xsrc[o];
    __syncthreads();

    float mu = g_stats[0], rstd = g_stats[1];
    float aY0 = 0, aY1 = 0, aY2 = 0, aY3 = 0;
    float aZ0 = 0, aZ1 = 0, aZ2 = 0, aZ3 = 0;
    const float* x0 = Xs + (w * 4 + 0) * 256;
    const float* x1 = Xs + (w * 4 + 1) * 256;
    const float* x2 = Xs + (w * 4 + 2) * 256;
    const float* x3 = Xs + (w * 4 + 3) * 256;
    const float* w1p = W1s + lane * WSTRIDE;
    const float* w2p = W2s + lane * WSTRIDE;
    #pragma unroll 4
    for (int t = 0; t < 256; t += 4) {
        float4 w1 = *(const float4*)(w1p + t);
        float4 w2 = *(const float4*)(w2p + t);
        float4 xa = *(const float4*)(x0 + t);
        float4 xb = *(const float4*)(x1 + t);
        float4 xc = *(const float4*)(x2 + t);
        float4 xe = *(const float4*)(x3 + t);
        aY0 += xa.x*w1.x + xa.y*w1.y + xa.z*w1.z + xa.w*w1.w;
        aZ0 += xa.x*w2.x + xa.y*w2.y + xa.z*w2.z + xa.w*w2.w;
        aY1 += xb.x*w1.x + xb.y*w1.y + xb.z*w1.z + xb.w*w1.w;
        aZ1 += xb.x*w2.x + xb.y*w2.y + xb.z*w2.z + xb.w*w2.w;
        aY2 += xc.x*w1.x + xc.y*w1.y + xc.z*w1.z + xc.w*w1.w;
        aZ2 += xc.x*w2.x + xc.y*w2.y + xc.z*w2.z + xc.w*w2.w;
        aY3 += xe.x*w1.x + xe.y*w1.y + xe.z*w1.z + xe.w*w1.w;
        aZ3 += xe.x*w2.x + xe.y*w2.y + xe.z*w2.z + xe.w*w2.w;
    }
    float c1 = mu * g_w1sum[lane];
    float c2 = mu * g_w2sum[lane];
    float bs = g_bS[lane];
    int r0 = rbase + w * 4;
    g_Y[(r0 + 0) * 32 + lane] = rstd * (aY0 - c1);
    g_Y[(r0 + 1) * 32 + lane] = rstd * (aY1 - c1);
    g_Y[(r0 + 2) * 32 + lane] = rstd * (aY2 - c1);
    g_Y[(r0 + 3) * 32 + lane] = rstd * (aY3 - c1);
    g_Z[(r0 + 0) * 32 + lane] = rstd * (aZ0 - c2) + bs;
    g_Z[(r0 + 1) * 32 + lane] = rstd * (aZ1 - c2) + bs;
    g_Z[(r0 + 2) * 32 + lane] = rstd * (aZ2 - c2) + bs;
    g_Z[(r0 + 3) * 32 + lane] = rstd * (aZ3 - c2) + bs;
}

// ---------------- K5a: stream A -> CSR + dinv (streaming loads) ----------------
__global__ void __launch_bounds__(256) k5a(const float* __restrict__ A) {
    int i = blockIdx.x;
    int tid = threadIdx.x, lane = tid & 31, wid = tid >> 5;
    __shared__ int s_warp[8];
    __shared__ int s_total;

    const float4* arow = (const float4*)(A + (size_t)i * N_NODES);
    unsigned mask = 0;
    #pragma unroll
    for (int u = 0; u < 8; u++) {
        float4 v = __ldcs(&arow[u * 256 + tid]);   // streaming, evict-first
        unsigned bb = (v.x != 0.f) | ((v.y != 0.f) << 1) |
                      ((v.z != 0.f) << 2) | ((v.w != 0.f) << 3);
        mask |= bb << (u * 4);
    }
    int cntL = __popc(mask);

    int incl = cntL;
    for (int o = 1; o < 32; o <<= 1) {
        int n = __shfl_up_sync(0xffffffffu, incl, o);
        if (lane >= o) incl += n;
    }
    if (lane == 31) s_warp[wid] = incl;
    __syncthreads();
    if (tid < 8) {
        int wv = s_warp[tid];
        int inc = wv;
        for (int o = 1; o < 8; o <<= 1) {
            int n = __shfl_up_sync(0xffu, inc, o);
            if (tid >= o) inc += n;
        }
        if (tid == 7) s_total = inc;
        s_warp[tid] = inc - wv;
    }
    __syncthreads();

    size_t rowbase = (size_t)i * MAXDEG;
    int p = s_warp[wid] + (incl - cntL);
    unsigned m = mask;
    while (m) {
        int bb = __ffs(m) - 1;
        m &= m - 1;
        int col = ((bb >> 2) << 10) + (tid << 2) + (bb & 3);
        if (p < MAXDEG) g_nz[rowbase + p++] = col;
    }
    if (tid == 0) {
        int total = s_total;
        if (total > MAXDEG) total = MAXDEG;
        g_cnt[i] = total;
        g_dinv[i] = rsqrtf((float)total);   // A is 0/1: degree == nnz
    }
}

// ---------------- K5b: gather + softmax + w-vector + rowden ----------------
__global__ void __launch_bounds__(256) k5b(float* __restrict__ out) {
    int tid = threadIdx.x, lane = tid & 31, w = tid >> 5;
    int i = blockIdx.x * 8 + w;

    int cnt = g_cnt[i];
    const size_t base = (size_t)i * MAXDEG;
    float a0 = 0.f, a1 = 0.f, a2 = 0.f, a3 = 0.f;
    float a4 = 0.f, a5 = 0.f, a6 = 0.f, a7 = 0.f;
    float accd = 0.f;

    for (int kk = 0; kk < cnt; kk += 32) {
        int rem = cnt - kk; if (rem > 32) rem = 32;
        int valid = (kk + lane) < cnt;
        int idx = valid ? g_nz[base + kk + lane] : 0;
        accd += valid ? g_dinv[idx] : 0.f;
        int g = 0;
        for (; g + 8 <= rem; g += 8) {
            int j0 = __shfl_sync(0xffffffffu, idx, g + 0);
            int j1 = __shfl_sync(0xffffffffu, idx, g + 1);
            int j2 = __shfl_sync(0xffffffffu, idx, g + 2);
            int j3 = __shfl_sync(0xffffffffu, idx, g + 3);
            int j4 = __shfl_sync(0xffffffffu, idx, g + 4);
            int j5 = __shfl_sync(0xffffffffu, idx, g + 5);
            int j6 = __shfl_sync(0xffffffffu, idx, g + 6);
            int j7 = __shfl_sync(0xffffffffu, idx, g + 7);
            a0 += g_Y[j0 * 32 + lane];
            a1 += g_Y[j1 * 32 + lane];
            a2 += g_Y[j2 * 32 + lane];
            a3 += g_Y[j3 * 32 + lane];
            a4 += g_Y[j4 * 32 + lane];
            a5 += g_Y[j5 * 32 + lane];
            a6 += g_Y[j6 * 32 + lane];
            a7 += g_Y[j7 * 32 + lane];
        }
        for (; g < rem; g++) {
            int j = __shfl_sync(0xffffffffu, idx, g);
            a0 += g_Y[j * 32 + lane];
        }
    }
    float Sv = (((a0 + a1) + (a2 + a3)) + ((a4 + a5) + (a6 + a7))) + g_Z[i * 32 + lane];
    out[(size_t)i * 32 + lane] = Sv;        // output S

    float mx = Sv;
    #pragma unroll
    for (int o = 16; o > 0; o >>= 1) mx = fmaxf(mx, __shfl_xor_sync(0xffffffffu, mx, o));
    float e = expf(Sv - mx);
    float ssum = e;
    #pragma unroll
    for (int o = 16; o > 0; o >>= 1) ssum += __shfl_xor_sync(0xffffffffu, ssum, o);
    float sv = e / ssum;
    float di = g_dinv[i];
    g_s[i * 32 + lane] = sv;
    g_w[i * 32 + lane] = di * sv;           // w_j = dinv_j * s_j

    // rowden_i = dinv_i * (sum_j dinv_j) * ||s_i||^2
    float nsq = sv * sv;
    #pragma unroll
    for (int o = 16; o > 0; o >>= 1) nsq += __shfl_xor_sync(0xffffffffu, nsq, o);
    #pragma unroll
    for (int o = 16; o > 0; o >>= 1) accd += __shfl_xor_sync(0xffffffffu, accd, o);
    if (lane == 0) g_rowden[i] = di * accd * nsq;
}

// ---------------- K678: rownum (w-gather) + s^T s partials + finalize ----------------
__global__ void __launch_bounds__(256) k678(float* __restrict__ out) {
    int b = blockIdx.x;
    int tid = threadIdx.x, lane = tid & 31, w = tid >> 5;

    // ---- rownum: row i, pure w-row accumulate ----
    int i = b * 8 + w;
    float si = g_s[i * 32 + lane];
    float di = g_dinv[i];
    int cnt = g_cnt[i];
    const size_t base = (size_t)i * MAXDEG;
    float n0 = 0.f, n1 = 0.f, n2 = 0.f, n3 = 0.f;
    float n4 = 0.f, n5 = 0.f, n6 = 0.f, n7 = 0.f;

    for (int kk = 0; kk < cnt; kk += 32) {
        int rem = cnt - kk; if (rem > 32) rem = 32;
        int idx = (kk + lane < cnt) ? g_nz[base + kk + lane] : 0;
        int g = 0;
        for (; g + 8 <= rem; g += 8) {
            int j0 = __shfl_sync(0xffffffffu, idx, g + 0);
            int j1 = __shfl_sync(0xffffffffu, idx, g + 1);
            int j2 = __shfl_sync(0xffffffffu, idx, g + 2);
            int j3 = __shfl_sync(0xffffffffu, idx, g + 3);
            int j4 = __shfl_sync(0xffffffffu, idx, g + 4);
            int j5 = __shfl_sync(0xffffffffu, idx, g + 5);
            int j6 = __shfl_sync(0xffffffffu, idx, g + 6);
            int j7 = __shfl_sync(0xffffffffu, idx, g + 7);
            n0 += g_w[j0 * 32 + lane];
            n1 += g_w[j1 * 32 + lane];
            n2 += g_w[j2 * 32 + lane];
            n3 += g_w[j3 * 32 + lane];
            n4 += g_w[j4 * 32 + lane];
            n5 += g_w[j5 * 32 + lane];
            n6 += g_w[j6 * 32 + lane];
            n7 += g_w[j7 * 32 + lane];
        }
        for (; g < rem; g++) {
            int j = __shfl_sync(0xffffffffu, idx, g);
            n0 += g_w[j * 32 + lane];
        }
    }
    float an = si * ((((n0 + n1) + (n2 + n3)) + ((n4 + n5) + (n6 + n7))));
    #pragma unroll
    for (int o = 16; o > 0; o >>= 1) an += __shfl_xor_sync(0xffffffffu, an, o);
    if (lane == 0) g_rownum[i] = di * an;

    // ---- sTs partial: (c1, chunk) slice over 256 rows ----
    int c1 = b & 31, chunk = b >> 5;
    float acc = 0.f;
    int iend = chunk * 256 + 256;
    for (int ii = chunk * 256 + w; ii < iend; ii += 8)
        acc += g_s[ii * 32 + c1] * g_s[ii * 32 + lane];
    __shared__ float red[256];
    red[tid] = acc;
    __syncthreads();
    for (int o = 128; o >= 32; o >>= 1) {
        if (tid < o) red[tid] += red[tid + o];
        __syncthreads();
    }
    if (tid < 32) g_sspart[b * 32 + tid] = red[tid];

    __shared__ bool isLast;
    if (tid == 0) {
        __threadfence();
        isLast = (atomicAdd(&g_arr2, 1) == 1023);
    }
    __syncthreads();
    if (!isLast) return;

    // ---- finalize losses ----
    __shared__ float sd[256];
    __shared__ float s_num, s_den, s_frob;

    float an2 = 0.f, ad2 = 0.f;
    for (int k = tid; k < N_NODES; k += 256) {
        an2 += g_rownum[k];
        ad2 += g_rowden[k];
    }
    sd[tid] = an2;
    __syncthreads();
    for (int o = 128; o > 0; o >>= 1) { if (tid < o) sd[tid] += sd[tid + o]; __syncthreads(); }
    if (tid == 0) s_num = sd[0];
    __syncthreads();
    sd[tid] = ad2;
    __syncthreads();
    for (int o = 128; o > 0; o >>= 1) { if (tid < o) sd[tid] += sd[tid + o]; __syncthreads(); }
    if (tid == 0) s_den = sd[0];
    __syncthreads();

    float ssv[4];
    float fr = 0.f;
    #pragma unroll
    for (int u = 0; u < 4; u++) {
        int e = tid * 4 + u;
        int e1 = e >> 5, e2 = e & 31;
        float v = 0.f;
        #pragma unroll
        for (int ch = 0; ch < 32; ch++)
            v += g_sspart[((ch << 5) | e1) * 32 + e2];
        ssv[u] = v;
        fr += v * v;
    }
    sd[tid] = fr;
    __syncthreads();
    for (int o = 128; o > 0; o >>= 1) { if (tid < o) sd[tid] += sd[tid + o]; __syncthreads(); }
    if (tid == 0) s_frob = sqrtf(sd[0]);
    __syncthreads();

    float dsum = 0.f;
    #pragma unroll
    for (int u = 0; u < 4; u++) {
        int e = tid * 4 + u;
        int e1 = e >> 5, e2 = e & 31;
        float diff = ssv[u] / s_frob - ((e1 == e2) ? rsqrtf((float)C_DIM) : 0.f);
        dsum += diff * diff;
    }
    sd[tid] = dsum;
    __syncthreads();
    for (int o = 128; o > 0; o >>= 1) { if (tid < o) sd[tid] += sd[tid + o]; __syncthreads(); }

    if (tid == 0) {
        out[(size_t)N_NODES * C_DIM + 0] = -(s_num / s_den);   // loss_mc
        out[(size_t)N_NODES * C_DIM + 1] = sqrtf(sd[0]);       // loss_o
        g_arr2 = 0;
    }
}

// ---------------- launch (fork/join: X-chain overlaps A-stream) ----------------
extern "C" void kernel_launch(void* const* d_in, const int* in_sizes, int n_in,
                              void* d_out, int out_size) {
    const float* X     = (const float*)d_in[0];
    const float* A     = (const float*)d_in[1];
    const float* Wrel  = (const float*)d_in[2];
    const float* brel  = (const float*)d_in[3];
    const float* Wroot = (const float*)d_in[4];
    const float* Wmlp  = (const float*)d_in[5];
    const float* bmlp  = (const float*)d_in[6];
    float* out = (float*)d_out;

    const int K4_SMEM = (64 * WSTRIDE + 8192) * 4;   // 99328 B

    static cudaStream_t s1 = nullptr;
    static cudaEvent_t evF = nullptr, evJ = nullptr;
    if (s1 == nullptr) {
        cudaStreamCreateWithFlags(&s1, cudaStreamNonBlocking);
        cudaEventCreateWithFlags(&evF, cudaEventDisableTiming);
        cudaEventCreateWithFlags(&evJ, cudaEventDisableTiming);
        cudaFuncSetAttribute(k4_yz, cudaFuncAttributeMaxDynamicSharedMemorySize, K4_SMEM);
    }

    // fork: X-chain on s1, A-stream on the capture stream
    cudaEventRecord(evF, 0);
    cudaStreamWaitEvent(s1, evF, 0);
    kAB<<<1089, 256, 0, s1>>>(X, Wrel, brel, Wroot, Wmlp, bmlp);
    k4_yz<<<256, 256, K4_SMEM, s1>>>(X);
    cudaEventRecord(evJ, s1);

    k5a<<<N_NODES, 256>>>(A);               // overlaps with s1 work

    // join: k5b needs g_Y/g_Z (s1) and CSR (k5a)
    cudaStreamWaitEvent((cudaStream_t)0, evJ, 0);
    k5b<<<N_NODES / 8, 256>>>(out);
    k678<<<1024, 256>>>(out);
}